// round 3
// baseline (speedup 1.0000x reference)
#include <cuda_runtime.h>

#define NU 2048
#define NI 8192
#define NQ 64
#define NITER 30
#define NSWEEP 10

__device__ float g_M[NU * NI];
__device__ float g_Mt[NI * NU];
__device__ float g_S[NU * NU];
__device__ float g_T[NI * NQ];
__device__ float g_Q[NU * NQ];
__device__ float g_Bt[NI * NQ];
__device__ float g_QC[NU * NQ];
__device__ float g_G[NQ * NQ];
__device__ float g_L[NQ * NQ];
__device__ float g_C[NQ * NQ];
__device__ float g_du[NU];
__device__ float g_di[NI];
__device__ float g_mrow[NU];
__device__ float g_minv[NU];
__device__ float g_rinv[NU];
__device__ float g_bsum[NQ];

__global__ void zero_kernel(float* __restrict__ p, int n) {
    int i = blockIdx.x * 256 + threadIdx.x;
    if (i < n) p[i] = 0.0f;
}

__global__ void rowsum_du_kernel(const float* __restrict__ F) {
    __shared__ float red[256];
    int row = blockIdx.x, tid = threadIdx.x;
    float s = 0.0f;
    for (int j = tid; j < NI; j += 256) s += F[row * NI + j];
    red[tid] = s; __syncthreads();
    for (int off = 128; off > 0; off >>= 1) {
        if (tid < off) red[tid] += red[tid + off];
        __syncthreads();
    }
    if (tid == 0) g_du[row] = rsqrtf(red[0] + 1.0f);
}

__global__ void colsum_di_kernel(const float* __restrict__ F) {
    int j = blockIdx.x * 256 + threadIdx.x;
    float s = 0.0f;
    for (int i = 0; i < NU; i++) s += F[i * NI + j];
    g_di[j] = rsqrtf(s + 1.0f);
}

__global__ void build_M_kernel(const float* __restrict__ F) {
    __shared__ float sh[32][33];
    int tx = threadIdx.x, ty = threadIdx.y;
    int col0 = blockIdx.x * 32, row0 = blockIdx.y * 32;
    int j = col0 + tx;
    float dj = g_di[j];
#pragma unroll
    for (int k = 0; k < 4; k++) {
        int i = row0 + ty + k * 8;
        float v = g_du[i] * F[i * NI + j] * dj;
        g_M[i * NI + j] = v;
        sh[ty + k * 8][tx] = v;
    }
    __syncthreads();
#pragma unroll
    for (int k = 0; k < 4; k++) {
        int jj = col0 + ty + k * 8;
        g_Mt[jj * NU + row0 + tx] = sh[tx][ty + k * 8];
    }
}

__device__ __forceinline__ unsigned int hashu(unsigned int x) {
    x ^= x >> 16; x *= 0x7feb352dU; x ^= x >> 15; x *= 0x846ca68bU; x ^= x >> 16;
    return x;
}

__global__ void rng_kernel() {
    int gid = blockIdx.x * 256 + threadIdx.x;
    unsigned int h1 = hashu(2u * gid + 17u);
    unsigned int h2 = hashu(2u * gid + 18u);
    float u1 = ((h1 >> 9) + 0.5f) * (1.0f / 8388608.0f);
    float u2 = ((h2 >> 9) + 0.5f) * (1.0f / 8388608.0f);
    g_T[gid] = sqrtf(-2.0f * __logf(u1)) * __cosf(6.2831853f * u2);
}

// out[R,64] += A[R,K] @ W[K,64]; split-K over grid.y; out pre-zeroed.
__global__ __launch_bounds__(256) void skinny_gemm(
    float* __restrict__ out, const float* __restrict__ A,
    const float* __restrict__ W, int lda, int kchunk) {
    __shared__ float AsT[16][64];
    __shared__ float Ws[16][64];
    int tid = threadIdx.x;
    int tx = tid & 15, ty = tid >> 4;
    int row0 = blockIdx.x * 64;
    int kb0 = blockIdx.y * kchunk;
    int aR = tid >> 2, aC = tid & 3;
    int wK = tid >> 4, wQ = tid & 15;
    float acc[4][4] = {};
    for (int kb = kb0; kb < kb0 + kchunk; kb += 16) {
        float4 av = *(const float4*)(A + (row0 + aR) * lda + kb + aC * 4);
        AsT[aC * 4 + 0][aR] = av.x; AsT[aC * 4 + 1][aR] = av.y;
        AsT[aC * 4 + 2][aR] = av.z; AsT[aC * 4 + 3][aR] = av.w;
        *(float4*)(&Ws[wK][wQ * 4]) = *(const float4*)(W + (kb + wK) * NQ + wQ * 4);
        __syncthreads();
#pragma unroll
        for (int k = 0; k < 16; k++) {
            float4 a = *(float4*)&AsT[k][ty * 4];
            float4 w = *(float4*)&Ws[k][tx * 4];
            float aa[4] = {a.x, a.y, a.z, a.w};
            float ww[4] = {w.x, w.y, w.z, w.w};
#pragma unroll
            for (int i = 0; i < 4; i++)
#pragma unroll
                for (int j = 0; j < 4; j++) acc[i][j] += aa[i] * ww[j];
        }
        __syncthreads();
    }
#pragma unroll
    for (int i = 0; i < 4; i++)
#pragma unroll
        for (int j = 0; j < 4; j++)
            atomicAdd(&out[(row0 + ty * 4 + i) * NQ + tx * 4 + j], acc[i][j]);
}

// g_G += Y^T Y over 128 rows per block; g_G pre-zeroed.
__global__ __launch_bounds__(256) void gram_kernel(const float* __restrict__ Y) {
    __shared__ float Ys[16][64];
    int tid = threadIdx.x;
    int tx = tid & 15, ty = tid >> 4;
    int wK = tid >> 4, wQ = tid & 15;
    int base = blockIdx.x * 128;
    float acc[4][4] = {};
    for (int c = 0; c < 8; c++) {
        *(float4*)&Ys[wK][wQ * 4] =
            *(const float4*)(Y + (base + c * 16 + wK) * NQ + wQ * 4);
        __syncthreads();
#pragma unroll
        for (int r = 0; r < 16; r++) {
            float4 a = *(float4*)&Ys[r][ty * 4];
            float4 b = *(float4*)&Ys[r][tx * 4];
            float aa[4] = {a.x, a.y, a.z, a.w};
            float bb[4] = {b.x, b.y, b.z, b.w};
#pragma unroll
            for (int i = 0; i < 4; i++)
#pragma unroll
                for (int j = 0; j < 4; j++) acc[i][j] += aa[i] * bb[j];
        }
        __syncthreads();
    }
#pragma unroll
    for (int i = 0; i < 4; i++)
#pragma unroll
        for (int j = 0; j < 4; j++)
            atomicAdd(&g_G[(ty * 4 + i) * NQ + tx * 4 + j], acc[i][j]);
}

__global__ void chol_kernel() {
    __shared__ float sA[64][65];
    int tid = threadIdx.x;
    for (int j = 0; j < 64; j++) sA[tid][j] = g_G[tid * 64 + j];
    __syncthreads();
    for (int k = 0; k < 64; k++) {
        if (tid == k) sA[k][k] = sqrtf(fmaxf(sA[k][k], 1e-30f));
        __syncthreads();
        if (tid > k) sA[tid][k] /= sA[k][k];
        __syncthreads();
        if (tid > k)
            for (int j = k + 1; j <= tid; j++)
                sA[tid][j] -= sA[tid][k] * sA[j][k];
        __syncthreads();
    }
    for (int j = 0; j < 64; j++)
        g_L[tid * 64 + j] = (j <= tid) ? sA[tid][j] : 0.0f;
}

// Y <- Y * (L^T)^{-1}, one row per thread (forward substitution)
__global__ __launch_bounds__(256) void trsm_kernel(float* __restrict__ Y, int R) {
    __shared__ float sL[64 * 64];
    int tid = threadIdx.x;
    for (int i = tid; i < 4096; i += 256) sL[i] = g_L[i];
    __syncthreads();
    int gid = blockIdx.x * 256 + tid;
    if (gid >= R) return;
    float q[64];
#pragma unroll
    for (int j = 0; j < 64; j++) {
        float acc = Y[gid * NQ + j];
#pragma unroll
        for (int i = 0; i < 64; i++)
            if (i < j) acc -= q[i] * sL[j * 64 + i];
        q[j] = acc / sL[j * 64 + j];
    }
#pragma unroll
    for (int j = 0; j < 64; j++) Y[gid * NQ + j] = q[j];
}

// Jacobi eigensolve of g_G; g_C = V diag(lam^1.5/lammax^2) V^T
__global__ __launch_bounds__(256) void jacobi_kernel() {
    __shared__ float sA[64][65];
    __shared__ float sV[64][65];
    __shared__ float pc[32], ps[32];
    __shared__ int pp[32], pq[32];
    __shared__ float lam[64];
    __shared__ float smax;
    int tid = threadIdx.x;
    for (int o = tid; o < 4096; o += 256) {
        int r = o >> 6, c = o & 63;
        sA[r][c] = g_G[o];
        sV[r][c] = (r == c) ? 1.0f : 0.0f;
    }
    __syncthreads();
    for (int sweep = 0; sweep < NSWEEP; sweep++) {
        for (int r = 0; r < 63; r++) {
            if (tid < 32) {
                int p, q;
                if (tid == 0) { p = 63; q = r; }
                else { p = (r + tid) % 63; q = (r - tid + 63) % 63; }
                float app = sA[p][p], aqq = sA[q][q], apq = sA[p][q];
                float c = 1.0f, s = 0.0f;
                if (fabsf(apq) > 1e-20f) {
                    float tau = (aqq - app) / (2.0f * apq);
                    float t = ((tau >= 0.0f) ? 1.0f : -1.0f) /
                              (fabsf(tau) + sqrtf(1.0f + tau * tau));
                    c = rsqrtf(1.0f + t * t);
                    s = t * c;
                }
                pp[tid] = p; pq[tid] = q; pc[tid] = c; ps[tid] = s;
            }
            __syncthreads();
            for (int it = tid; it < 4096; it += 256) {
                int pr = it >> 7;
                int rest = it & 127;
                int i = rest & 63;
                float c = pc[pr], s = ps[pr];
                int p = pp[pr], q = pq[pr];
                if (rest < 64) {
                    float x = sA[i][p], y = sA[i][q];
                    sA[i][p] = c * x - s * y;
                    sA[i][q] = s * x + c * y;
                } else {
                    float x = sV[i][p], y = sV[i][q];
                    sV[i][p] = c * x - s * y;
                    sV[i][q] = s * x + c * y;
                }
            }
            __syncthreads();
            for (int it = tid; it < 2048; it += 256) {
                int pr = it >> 6;
                int j = it & 63;
                float c = pc[pr], s = ps[pr];
                int p = pp[pr], q = pq[pr];
                float x = sA[p][j], y = sA[q][j];
                sA[p][j] = c * x - s * y;
                sA[q][j] = s * x + c * y;
            }
            __syncthreads();
        }
    }
    if (tid < 64) lam[tid] = fmaxf(sA[tid][tid], 0.0f);
    __syncthreads();
    if (tid == 0) {
        float m = 0.0f;
        for (int k = 0; k < 64; k++) m = fmaxf(m, lam[k]);
        smax = m;
    }
    __syncthreads();
    if (tid < 64) {
        float l = lam[tid];
        lam[tid] = l * sqrtf(l) / (smax * smax);
    }
    __syncthreads();
    for (int o = tid; o < 4096; o += 256) {
        int i = o >> 6, j = o & 63;
        float acc = 0.0f;
        for (int k = 0; k < 64; k++) acc += sV[i][k] * lam[k] * sV[j][k];
        g_C[o] = acc;
    }
}

__global__ __launch_bounds__(256) void qc_kernel() {
    __shared__ float sC[64 * 64];
    int tid = threadIdx.x;
    for (int i = tid; i < 4096; i += 256) sC[i] = g_C[i];
    __syncthreads();
    int gid = blockIdx.x * 256 + tid;
    int i = gid >> 6, k2 = gid & 63;
    float acc = 0.0f;
    for (int k = 0; k < 64; k++) acc += g_Q[i * 64 + k] * sC[k * 64 + k2];
    g_QC[gid] = acc;
}

__global__ void colsum_bt_kernel() {
    __shared__ float red[256];
    int b = blockIdx.x, tid = threadIdx.x;
    float s = 0.0f;
    for (int r = tid; r < NI; r += 256) s += g_Bt[r * NQ + b];
    red[tid] = s; __syncthreads();
    for (int off = 128; off > 0; off >>= 1) {
        if (tid < off) red[tid] += red[tid + off];
        __syncthreads();
    }
    if (tid == 0) g_bsum[b] = red[0];
}

__global__ void rsuminv_kernel() {
    int gid = blockIdx.x * 256 + threadIdx.x;
    float acc = 0.0f;
    for (int k = 0; k < 64; k++) acc += g_QC[gid * 64 + k] * g_bsum[k];
    g_rinv[gid] = 1.0f / acc;
}

__global__ void rowsum_M_kernel() {
    __shared__ float red[256];
    int row = blockIdx.x, tid = threadIdx.x;
    float s = 0.0f;
    for (int j = tid; j < NI; j += 256) s += g_M[row * NI + j];
    red[tid] = s; __syncthreads();
    for (int off = 128; off > 0; off >>= 1) {
        if (tid < off) red[tid] += red[tid + off];
        __syncthreads();
    }
    if (tid == 0) g_mrow[row] = red[0];
}

__global__ void matvec_minv_kernel() {
    __shared__ float red[256];
    int row = blockIdx.x, tid = threadIdx.x;
    float s = 0.0f;
    for (int j = tid; j < NU; j += 256) s += g_S[row * NU + j] * g_mrow[j];
    red[tid] = s; __syncthreads();
    for (int off = 128; off > 0; off >>= 1) {
        if (tid < off) red[tid] += red[tid + off];
        __syncthreads();
    }
    if (tid == 0) g_minv[row] = 1.0f / red[0];
}

__global__ void scale_rows_kernel(float* __restrict__ p, const float* __restrict__ v,
                                  int cols, int n) {
    int gid = blockIdx.x * 256 + threadIdx.x;
    if (gid < n) p[gid] *= v[gid / cols];
}

// S = M M^T, 128x128 tiles
__global__ __launch_bounds__(256) void gemm_nt_S() {
    __shared__ float As[16][128];
    __shared__ float Bs[16][128];
    int tid = threadIdx.x;
    int tx = tid & 15, ty = tid >> 4;
    int row0 = blockIdx.y * 128, col0 = blockIdx.x * 128;
    float acc[8][8] = {};
    for (int kb = 0; kb < NI; kb += 16) {
#pragma unroll
        for (int l = 0; l < 2; l++) {
            int q = tid * 2 + l;
            int r = q >> 2, c = q & 3;
            float4 v = *(const float4*)(g_M + (row0 + r) * NI + kb + c * 4);
            As[c * 4 + 0][r] = v.x; As[c * 4 + 1][r] = v.y;
            As[c * 4 + 2][r] = v.z; As[c * 4 + 3][r] = v.w;
            float4 w = *(const float4*)(g_M + (col0 + r) * NI + kb + c * 4);
            Bs[c * 4 + 0][r] = w.x; Bs[c * 4 + 1][r] = w.y;
            Bs[c * 4 + 2][r] = w.z; Bs[c * 4 + 3][r] = w.w;
        }
        __syncthreads();
#pragma unroll
        for (int k = 0; k < 16; k++) {
            float4 a0 = *(float4*)&As[k][ty * 8];
            float4 a1 = *(float4*)&As[k][ty * 8 + 4];
            float4 b0 = *(float4*)&Bs[k][tx * 8];
            float4 b1 = *(float4*)&Bs[k][tx * 8 + 4];
            float ar[8] = {a0.x, a0.y, a0.z, a0.w, a1.x, a1.y, a1.z, a1.w};
            float br[8] = {b0.x, b0.y, b0.z, b0.w, b1.x, b1.y, b1.z, b1.w};
#pragma unroll
            for (int i = 0; i < 8; i++)
#pragma unroll
                for (int j = 0; j < 8; j++) acc[i][j] += ar[i] * br[j];
        }
        __syncthreads();
    }
#pragma unroll
    for (int i = 0; i < 8; i++) {
        int gr = row0 + ty * 8 + i;
        *(float4*)(g_S + gr * NU + col0 + tx * 8) =
            make_float4(acc[i][0], acc[i][1], acc[i][2], acc[i][3]);
        *(float4*)(g_S + gr * NU + col0 + tx * 8 + 4) =
            make_float4(acc[i][4], acc[i][5], acc[i][6], acc[i][7]);
    }
}

// out = sigmoid(S_s @ M + QC_s @ Bt^T) - 1000*F
__global__ __launch_bounds__(256) void final_kernel(const float* __restrict__ F,
                                                    float* __restrict__ out) {
    __shared__ float As[16][128];
    __shared__ float Bs[16][128];
    int tid = threadIdx.x;
    int tx = tid & 15, ty = tid >> 4;
    int row0 = blockIdx.y * 128, col0 = blockIdx.x * 128;
    float acc[8][8] = {};
    for (int kb = 0; kb < NU; kb += 16) {
#pragma unroll
        for (int l = 0; l < 2; l++) {
            int q = tid * 2 + l;
            int r = q >> 2, c = q & 3;
            float4 v = *(const float4*)(g_S + (row0 + r) * NU + kb + c * 4);
            As[c * 4 + 0][r] = v.x; As[c * 4 + 1][r] = v.y;
            As[c * 4 + 2][r] = v.z; As[c * 4 + 3][r] = v.w;
            int k2 = q >> 5, n = q & 31;
            *(float4*)&Bs[k2][n * 4] =
                *(const float4*)(g_M + (kb + k2) * NI + col0 + n * 4);
        }
        __syncthreads();
#pragma unroll
        for (int k = 0; k < 16; k++) {
            float4 a0 = *(float4*)&As[k][ty * 8];
            float4 a1 = *(float4*)&As[k][ty * 8 + 4];
            float4 b0 = *(float4*)&Bs[k][tx * 8];
            float4 b1 = *(float4*)&Bs[k][tx * 8 + 4];
            float ar[8] = {a0.x, a0.y, a0.z, a0.w, a1.x, a1.y, a1.z, a1.w};
            float br[8] = {b0.x, b0.y, b0.z, b0.w, b1.x, b1.y, b1.z, b1.w};
#pragma unroll
            for (int i = 0; i < 8; i++)
#pragma unroll
                for (int j = 0; j < 8; j++) acc[i][j] += ar[i] * br[j];
        }
        __syncthreads();
    }
    for (int kb = 0; kb < 64; kb += 16) {
#pragma unroll
        for (int l = 0; l < 2; l++) {
            int q = tid * 2 + l;
            int r = q >> 2, c = q & 3;
            float4 v = *(const float4*)(g_QC + (row0 + r) * NQ + kb + c * 4);
            As[c * 4 + 0][r] = v.x; As[c * 4 + 1][r] = v.y;
            As[c * 4 + 2][r] = v.z; As[c * 4 + 3][r] = v.w;
            float4 w = *(const float4*)(g_Bt + (col0 + r) * NQ + kb + c * 4);
            Bs[c * 4 + 0][r] = w.x; Bs[c * 4 + 1][r] = w.y;
            Bs[c * 4 + 2][r] = w.z; Bs[c * 4 + 3][r] = w.w;
        }
        __syncthreads();
#pragma unroll
        for (int k = 0; k < 16; k++) {
            float4 a0 = *(float4*)&As[k][ty * 8];
            float4 a1 = *(float4*)&As[k][ty * 8 + 4];
            float4 b0 = *(float4*)&Bs[k][tx * 8];
            float4 b1 = *(float4*)&Bs[k][tx * 8 + 4];
            float ar[8] = {a0.x, a0.y, a0.z, a0.w, a1.x, a1.y, a1.z, a1.w};
            float br[8] = {b0.x, b0.y, b0.z, b0.w, b1.x, b1.y, b1.z, b1.w};
#pragma unroll
            for (int i = 0; i < 8; i++)
#pragma unroll
                for (int j = 0; j < 8; j++) acc[i][j] += ar[i] * br[j];
        }
        __syncthreads();
    }
#pragma unroll
    for (int i = 0; i < 8; i++) {
        int gr = row0 + ty * 8 + i;
        int gc = col0 + tx * 8;
        float4 f0 = *(const float4*)(F + gr * NI + gc);
        float4 f1 = *(const float4*)(F + gr * NI + gc + 4);
        float4 o0, o1;
        o0.x = 1.0f / (1.0f + __expf(-acc[i][0])) - 1000.0f * f0.x;
        o0.y = 1.0f / (1.0f + __expf(-acc[i][1])) - 1000.0f * f0.y;
        o0.z = 1.0f / (1.0f + __expf(-acc[i][2])) - 1000.0f * f0.z;
        o0.w = 1.0f / (1.0f + __expf(-acc[i][3])) - 1000.0f * f0.w;
        o1.x = 1.0f / (1.0f + __expf(-acc[i][4])) - 1000.0f * f1.x;
        o1.y = 1.0f / (1.0f + __expf(-acc[i][5])) - 1000.0f * f1.y;
        o1.z = 1.0f / (1.0f + __expf(-acc[i][6])) - 1000.0f * f1.z;
        o1.w = 1.0f / (1.0f + __expf(-acc[i][7])) - 1000.0f * f1.w;
        *(float4*)(out + gr * NI + gc) = o0;
        *(float4*)(out + gr * NI + gc + 4) = o1;
    }
}

static void cholqr(float* Y, int R) {
    float* pG; cudaGetSymbolAddress((void**)&pG, g_G);
    zero_kernel<<<(NQ * NQ + 255) / 256, 256>>>(pG, NQ * NQ);
    gram_kernel<<<R / 128, 256>>>(Y);
    chol_kernel<<<1, 64>>>();
    trsm_kernel<<<R / 256, 256>>>(Y, R);
}

extern "C" void kernel_launch(void* const* d_in, const int* in_sizes, int n_in,
                              void* d_out, int out_size) {
    (void)in_sizes; (void)n_in; (void)out_size;
    const float* F = (const float*)d_in[0];
    float* out = (float*)d_out;

    float *pM, *pMt, *pT, *pQ, *pBt, *pQC, *pS, *pRinv, *pMinv;
    cudaGetSymbolAddress((void**)&pM, g_M);
    cudaGetSymbolAddress((void**)&pMt, g_Mt);
    cudaGetSymbolAddress((void**)&pT, g_T);
    cudaGetSymbolAddress((void**)&pQ, g_Q);
    cudaGetSymbolAddress((void**)&pBt, g_Bt);
    cudaGetSymbolAddress((void**)&pQC, g_QC);
    cudaGetSymbolAddress((void**)&pS, g_S);
    cudaGetSymbolAddress((void**)&pRinv, g_rinv);
    cudaGetSymbolAddress((void**)&pMinv, g_minv);

    // normalization + M/Mt
    rowsum_du_kernel<<<NU, 256>>>(F);
    colsum_di_kernel<<<NI / 256, 256>>>(F);
    build_M_kernel<<<dim3(NI / 32, NU / 32), dim3(32, 8)>>>(F);

    // Q0 = cholQR(M @ R)
    rng_kernel<<<(NI * NQ) / 256, 256>>>();
    zero_kernel<<<(NU * NQ) / 256, 256>>>(pQ, NU * NQ);
    skinny_gemm<<<dim3(NU / 64, 8), 256>>>(pQ, pM, pT, NI, NI / 8);
    cholqr(pQ, NU);

    // subspace iterations
    for (int it = 0; it < NITER; it++) {
        zero_kernel<<<(NI * NQ) / 256, 256>>>(pT, NI * NQ);
        skinny_gemm<<<dim3(NI / 64, 2), 256>>>(pT, pMt, pQ, NU, NU / 2);
        cholqr(pT, NI);
        zero_kernel<<<(NU * NQ) / 256, 256>>>(pQ, NU * NQ);
        skinny_gemm<<<dim3(NU / 64, 8), 256>>>(pQ, pM, pT, NI, NI / 8);
        cholqr(pQ, NU);
    }

    // Bt = M^T Q; G = Bt^T Bt; eigensolve -> C; QC = Q C
    zero_kernel<<<(NI * NQ) / 256, 256>>>(pBt, NI * NQ);
    skinny_gemm<<<dim3(NI / 64, 2), 256>>>(pBt, pMt, pQ, NU, NU / 2);
    {
        float* pG; cudaGetSymbolAddress((void**)&pG, g_G);
        zero_kernel<<<(NQ * NQ + 255) / 256, 256>>>(pG, NQ * NQ);
        gram_kernel<<<NI / 128, 256>>>(pBt);
    }
    jacobi_kernel<<<1, 256>>>();
    qc_kernel<<<(NU * NQ) / 256, 256>>>();

    // rate row-sum inverse, fold into QC rows
    colsum_bt_kernel<<<NQ, 256>>>();
    rsuminv_kernel<<<NU / 256, 256>>>();
    scale_rows_kernel<<<(NU * NQ) / 256, 256>>>(pQC, pRinv, NQ, NU * NQ);

    // S = M M^T, fold 1/m3sum into S rows
    gemm_nt_S<<<dim3(NU / 128, NU / 128), 256>>>();
    rowsum_M_kernel<<<NU, 256>>>();
    matvec_minv_kernel<<<NU, 256>>>();
    scale_rows_kernel<<<(NU * NU) / 256, 256>>>(pS, pMinv, NU, NU * NU);

    // fused final: out = sigmoid(S M + QC Bt^T) - 1000 F
    final_kernel<<<dim3(NI / 128, NU / 128), 256>>>(F, out);
}

// round 4
// speedup vs baseline: 1.6827x; 1.6827x over previous
#include <cuda_runtime.h>

#define NU 2048
#define NI 8192
#define NQ 64
#define NITER 30
#define NSWEEP 10

__device__ float g_M[NU * NI];
__device__ float g_Mt[NI * NU];
__device__ float g_S[NU * NU];
__device__ float g_Q[NU * NQ];
__device__ float g_Q2[NU * NQ];
__device__ float g_Bt[NI * NQ];
__device__ float g_QC[NU * NQ];
__device__ float g_G[NQ * NQ];
__device__ float g_Gp[16 * NQ * NQ];
__device__ float g_Li[NQ * NQ];
__device__ float g_C[NQ * NQ];
__device__ float g_du[NU];
__device__ float g_di[NI];
__device__ float g_mrow[NU];
__device__ float g_minv[NU];
__device__ float g_rinv[NU];
__device__ float g_bsum[NQ];

__global__ void zero_kernel(float* __restrict__ p, int n) {
    int i = blockIdx.x * 256 + threadIdx.x;
    if (i < n) p[i] = 0.0f;
}

__global__ void rowsum_du_kernel(const float* __restrict__ F) {
    __shared__ float red[256];
    int row = blockIdx.x, tid = threadIdx.x;
    float s = 0.0f;
    for (int j = tid; j < NI; j += 256) s += F[row * NI + j];
    red[tid] = s; __syncthreads();
    for (int off = 128; off > 0; off >>= 1) {
        if (tid < off) red[tid] += red[tid + off];
        __syncthreads();
    }
    if (tid == 0) g_du[row] = rsqrtf(red[0] + 1.0f);
}

__global__ void colsum_di_kernel(const float* __restrict__ F) {
    int j = blockIdx.x * 256 + threadIdx.x;
    float s = 0.0f;
    for (int i = 0; i < NU; i++) s += F[i * NI + j];
    g_di[j] = rsqrtf(s + 1.0f);
}

__global__ void build_M_kernel(const float* __restrict__ F) {
    __shared__ float sh[32][33];
    int tx = threadIdx.x, ty = threadIdx.y;
    int col0 = blockIdx.x * 32, row0 = blockIdx.y * 32;
    int j = col0 + tx;
    float dj = g_di[j];
#pragma unroll
    for (int k = 0; k < 4; k++) {
        int i = row0 + ty + k * 8;
        float v = g_du[i] * F[i * NI + j] * dj;
        g_M[i * NI + j] = v;
        sh[ty + k * 8][tx] = v;
    }
    __syncthreads();
#pragma unroll
    for (int k = 0; k < 4; k++) {
        int jj = col0 + ty + k * 8;
        g_Mt[jj * NU + row0 + tx] = sh[tx][ty + k * 8];
    }
}

__device__ __forceinline__ unsigned int hashu(unsigned int x) {
    x ^= x >> 16; x *= 0x7feb352dU; x ^= x >> 15; x *= 0x846ca68bU; x ^= x >> 16;
    return x;
}

__global__ void rng_kernel(float* __restrict__ p) {
    int gid = blockIdx.x * 256 + threadIdx.x;
    unsigned int h1 = hashu(2u * gid + 17u);
    unsigned int h2 = hashu(2u * gid + 18u);
    float u1 = ((h1 >> 9) + 0.5f) * (1.0f / 8388608.0f);
    float u2 = ((h2 >> 9) + 0.5f) * (1.0f / 8388608.0f);
    p[gid] = sqrtf(-2.0f * __logf(u1)) * __cosf(6.2831853f * u2);
}

// out[R,64] += A[R,K] @ W[K,64]; split-K over grid.y; out pre-zeroed.
__global__ __launch_bounds__(256) void skinny_gemm(
    float* __restrict__ out, const float* __restrict__ A,
    const float* __restrict__ W, int lda, int kchunk) {
    __shared__ float AsT[16][64];
    __shared__ float Ws[16][64];
    int tid = threadIdx.x;
    int tx = tid & 15, ty = tid >> 4;
    int row0 = blockIdx.x * 64;
    int kb0 = blockIdx.y * kchunk;
    int aR = tid >> 2, aC = tid & 3;
    int wK = tid >> 4, wQ = tid & 15;
    float acc[4][4] = {};
    for (int kb = kb0; kb < kb0 + kchunk; kb += 16) {
        float4 av = *(const float4*)(A + (row0 + aR) * lda + kb + aC * 4);
        AsT[aC * 4 + 0][aR] = av.x; AsT[aC * 4 + 1][aR] = av.y;
        AsT[aC * 4 + 2][aR] = av.z; AsT[aC * 4 + 3][aR] = av.w;
        *(float4*)(&Ws[wK][wQ * 4]) = *(const float4*)(W + (kb + wK) * NQ + wQ * 4);
        __syncthreads();
#pragma unroll
        for (int k = 0; k < 16; k++) {
            float4 a = *(float4*)&AsT[k][ty * 4];
            float4 w = *(float4*)&Ws[k][tx * 4];
            float aa[4] = {a.x, a.y, a.z, a.w};
            float ww[4] = {w.x, w.y, w.z, w.w};
#pragma unroll
            for (int i = 0; i < 4; i++)
#pragma unroll
                for (int j = 0; j < 4; j++) acc[i][j] += aa[i] * ww[j];
        }
        __syncthreads();
    }
#pragma unroll
    for (int i = 0; i < 4; i++)
#pragma unroll
        for (int j = 0; j < 4; j++)
            atomicAdd(&out[(row0 + ty * 4 + i) * NQ + tx * 4 + j], acc[i][j]);
}

// atomic Gram into g_G (used once, for Bt)
__global__ __launch_bounds__(256) void gram_kernel(const float* __restrict__ Y) {
    __shared__ float Ys[16][64];
    int tid = threadIdx.x;
    int tx = tid & 15, ty = tid >> 4;
    int wK = tid >> 4, wQ = tid & 15;
    int base = blockIdx.x * 128;
    float acc[4][4] = {};
    for (int c = 0; c < 8; c++) {
        *(float4*)&Ys[wK][wQ * 4] =
            *(const float4*)(Y + (base + c * 16 + wK) * NQ + wQ * 4);
        __syncthreads();
#pragma unroll
        for (int r = 0; r < 16; r++) {
            float4 a = *(float4*)&Ys[r][ty * 4];
            float4 b = *(float4*)&Ys[r][tx * 4];
            float aa[4] = {a.x, a.y, a.z, a.w};
            float bb[4] = {b.x, b.y, b.z, b.w};
#pragma unroll
            for (int i = 0; i < 4; i++)
#pragma unroll
                for (int j = 0; j < 4; j++) acc[i][j] += aa[i] * bb[j];
        }
        __syncthreads();
    }
#pragma unroll
    for (int i = 0; i < 4; i++)
#pragma unroll
        for (int j = 0; j < 4; j++)
            atomicAdd(&g_G[(ty * 4 + i) * NQ + tx * 4 + j], acc[i][j]);
}

// per-block Gram partials (no atomics) for the QR loop (NU rows -> 16 blocks)
__global__ __launch_bounds__(256) void gram_part_kernel(const float* __restrict__ Y) {
    __shared__ float Ys[16][64];
    int tid = threadIdx.x;
    int tx = tid & 15, ty = tid >> 4;
    int wK = tid >> 4, wQ = tid & 15;
    int base = blockIdx.x * 128;
    float acc[4][4] = {};
    for (int c = 0; c < 8; c++) {
        *(float4*)&Ys[wK][wQ * 4] =
            *(const float4*)(Y + (base + c * 16 + wK) * NQ + wQ * 4);
        __syncthreads();
#pragma unroll
        for (int r = 0; r < 16; r++) {
            float4 a = *(float4*)&Ys[r][ty * 4];
            float4 b = *(float4*)&Ys[r][tx * 4];
            float aa[4] = {a.x, a.y, a.z, a.w};
            float bb[4] = {b.x, b.y, b.z, b.w};
#pragma unroll
            for (int i = 0; i < 4; i++)
#pragma unroll
                for (int j = 0; j < 4; j++) acc[i][j] += aa[i] * bb[j];
        }
        __syncthreads();
    }
    float* dst = g_Gp + blockIdx.x * (NQ * NQ);
#pragma unroll
    for (int i = 0; i < 4; i++)
#pragma unroll
        for (int j = 0; j < 4; j++)
            dst[(ty * 4 + i) * NQ + tx * 4 + j] = acc[i][j];
}

// sum Gram partials -> Cholesky L -> explicit Linv (lower). 64 threads.
__global__ void chol_linv_kernel(int nparts) {
    __shared__ float sA[64][65];
    int tid = threadIdx.x;
    for (int j = 0; j < 64; j++) {
        float s = 0.0f;
        for (int p = 0; p < nparts; p++) s += g_Gp[p * 4096 + tid * 64 + j];
        sA[tid][j] = s;
    }
    __syncthreads();
    for (int k = 0; k < 64; k++) {
        if (tid == k) sA[k][k] = sqrtf(fmaxf(sA[k][k], 1e-30f));
        __syncthreads();
        if (tid > k) sA[tid][k] /= sA[k][k];
        __syncthreads();
        if (tid > k)
            for (int j = k + 1; j <= tid; j++)
                sA[tid][j] -= sA[tid][k] * sA[j][k];
        __syncthreads();
    }
    // thread c computes column c of Linv (lower triangular)
    float x[64];
    int c = tid;
    for (int i = 0; i < 64; i++) x[i] = 0.0f;
    x[c] = 1.0f / sA[c][c];
    for (int i = c + 1; i < 64; i++) {
        float acc = 0.0f;
        for (int k = c; k < i; k++) acc += sA[i][k] * x[k];
        x[i] = -acc / sA[i][i];
    }
    for (int i = 0; i < 64; i++) g_Li[i * 64 + c] = x[i];
}

// Y <- Y * Linv^T  (i.e. Ynew[r][j] = sum_{k<=j} Y[r][k]*Linv[j][k]); 4 rows/block
__global__ __launch_bounds__(256) void trsm_apply_kernel(float* __restrict__ Y) {
    __shared__ float sLi[64][65];
    __shared__ float sY[4][64];
    int tid = threadIdx.x;
    for (int i = tid; i < 4096; i += 256) sLi[i >> 6][i & 63] = g_Li[i];
    int lr = tid >> 6, j = tid & 63;
    int r = blockIdx.x * 4 + lr;
    sY[lr][j] = Y[r * NQ + j];
    __syncthreads();
    float acc = 0.0f;
    for (int k = 0; k <= j; k++) acc += sY[lr][k] * sLi[j][k];
    Y[r * NQ + j] = acc;
}

// Jacobi eigensolve of g_G; g_C = V diag(lam^1.5/lammax^2) V^T
__global__ __launch_bounds__(256) void jacobi_kernel() {
    __shared__ float sA[64][65];
    __shared__ float sV[64][65];
    __shared__ float pc[32], ps[32];
    __shared__ int pp[32], pq[32];
    __shared__ float lam[64];
    __shared__ float smax;
    int tid = threadIdx.x;
    for (int o = tid; o < 4096; o += 256) {
        int r = o >> 6, c = o & 63;
        sA[r][c] = g_G[o];
        sV[r][c] = (r == c) ? 1.0f : 0.0f;
    }
    __syncthreads();
    for (int sweep = 0; sweep < NSWEEP; sweep++) {
        for (int r = 0; r < 63; r++) {
            if (tid < 32) {
                int p, q;
                if (tid == 0) { p = 63; q = r; }
                else { p = (r + tid) % 63; q = (r - tid + 63) % 63; }
                float app = sA[p][p], aqq = sA[q][q], apq = sA[p][q];
                float c = 1.0f, s = 0.0f;
                if (fabsf(apq) > 1e-20f) {
                    float tau = (aqq - app) / (2.0f * apq);
                    float t = ((tau >= 0.0f) ? 1.0f : -1.0f) /
                              (fabsf(tau) + sqrtf(1.0f + tau * tau));
                    c = rsqrtf(1.0f + t * t);
                    s = t * c;
                }
                pp[tid] = p; pq[tid] = q; pc[tid] = c; ps[tid] = s;
            }
            __syncthreads();
            for (int it = tid; it < 4096; it += 256) {
                int pr = it >> 7;
                int rest = it & 127;
                int i = rest & 63;
                float c = pc[pr], s = ps[pr];
                int p = pp[pr], q = pq[pr];
                if (rest < 64) {
                    float x = sA[i][p], y = sA[i][q];
                    sA[i][p] = c * x - s * y;
                    sA[i][q] = s * x + c * y;
                } else {
                    float x = sV[i][p], y = sV[i][q];
                    sV[i][p] = c * x - s * y;
                    sV[i][q] = s * x + c * y;
                }
            }
            __syncthreads();
            for (int it = tid; it < 2048; it += 256) {
                int pr = it >> 6;
                int j = it & 63;
                float c = pc[pr], s = ps[pr];
                int p = pp[pr], q = pq[pr];
                float x = sA[p][j], y = sA[q][j];
                sA[p][j] = c * x - s * y;
                sA[q][j] = s * x + c * y;
            }
            __syncthreads();
        }
    }
    if (tid < 64) lam[tid] = fmaxf(sA[tid][tid], 0.0f);
    __syncthreads();
    if (tid == 0) {
        float m = 0.0f;
        for (int k = 0; k < 64; k++) m = fmaxf(m, lam[k]);
        smax = m;
    }
    __syncthreads();
    if (tid < 64) {
        float l = lam[tid];
        lam[tid] = l * sqrtf(l) / (smax * smax);
    }
    __syncthreads();
    for (int o = tid; o < 4096; o += 256) {
        int i = o >> 6, j = o & 63;
        float acc = 0.0f;
        for (int k = 0; k < 64; k++) acc += sV[i][k] * lam[k] * sV[j][k];
        g_C[o] = acc;
    }
}

__global__ __launch_bounds__(256) void qc_kernel() {
    __shared__ float sC[64 * 64];
    int tid = threadIdx.x;
    for (int i = tid; i < 4096; i += 256) sC[i] = g_C[i];
    __syncthreads();
    int gid = blockIdx.x * 256 + tid;
    int i = gid >> 6, k2 = gid & 63;
    float acc = 0.0f;
    for (int k = 0; k < 64; k++) acc += g_Q[i * 64 + k] * sC[k * 64 + k2];
    g_QC[gid] = acc;
}

__global__ void colsum_bt_kernel() {
    __shared__ float red[256];
    int b = blockIdx.x, tid = threadIdx.x;
    float s = 0.0f;
    for (int r = tid; r < NI; r += 256) s += g_Bt[r * NQ + b];
    red[tid] = s; __syncthreads();
    for (int off = 128; off > 0; off >>= 1) {
        if (tid < off) red[tid] += red[tid + off];
        __syncthreads();
    }
    if (tid == 0) g_bsum[b] = red[0];
}

__global__ void rsuminv_kernel() {
    int gid = blockIdx.x * 256 + threadIdx.x;
    float acc = 0.0f;
    for (int k = 0; k < 64; k++) acc += g_QC[gid * 64 + k] * g_bsum[k];
    g_rinv[gid] = 1.0f / acc;
}

__global__ void rowsum_M_kernel() {
    __shared__ float red[256];
    int row = blockIdx.x, tid = threadIdx.x;
    float s = 0.0f;
    for (int j = tid; j < NI; j += 256) s += g_M[row * NI + j];
    red[tid] = s; __syncthreads();
    for (int off = 128; off > 0; off >>= 1) {
        if (tid < off) red[tid] += red[tid + off];
        __syncthreads();
    }
    if (tid == 0) g_mrow[row] = red[0];
}

__global__ void matvec_minv_kernel() {
    __shared__ float red[256];
    int row = blockIdx.x, tid = threadIdx.x;
    float s = 0.0f;
    for (int j = tid; j < NU; j += 256) s += g_S[row * NU + j] * g_mrow[j];
    red[tid] = s; __syncthreads();
    for (int off = 128; off > 0; off >>= 1) {
        if (tid < off) red[tid] += red[tid + off];
        __syncthreads();
    }
    if (tid == 0) g_minv[row] = 1.0f / red[0];
}

__global__ void scale_rows_kernel(float* __restrict__ p, const float* __restrict__ v,
                                  int cols, int n) {
    int gid = blockIdx.x * 256 + threadIdx.x;
    if (gid < n) p[gid] *= v[gid / cols];
}

// S = M M^T, 128x128 tiles
__global__ __launch_bounds__(256) void gemm_nt_S() {
    __shared__ float As[16][128];
    __shared__ float Bs[16][128];
    int tid = threadIdx.x;
    int tx = tid & 15, ty = tid >> 4;
    int row0 = blockIdx.y * 128, col0 = blockIdx.x * 128;
    float acc[8][8] = {};
    for (int kb = 0; kb < NI; kb += 16) {
#pragma unroll
        for (int l = 0; l < 2; l++) {
            int q = tid * 2 + l;
            int r = q >> 2, c = q & 3;
            float4 v = *(const float4*)(g_M + (row0 + r) * NI + kb + c * 4);
            As[c * 4 + 0][r] = v.x; As[c * 4 + 1][r] = v.y;
            As[c * 4 + 2][r] = v.z; As[c * 4 + 3][r] = v.w;
            float4 w = *(const float4*)(g_M + (col0 + r) * NI + kb + c * 4);
            Bs[c * 4 + 0][r] = w.x; Bs[c * 4 + 1][r] = w.y;
            Bs[c * 4 + 2][r] = w.z; Bs[c * 4 + 3][r] = w.w;
        }
        __syncthreads();
#pragma unroll
        for (int k = 0; k < 16; k++) {
            float4 a0 = *(float4*)&As[k][ty * 8];
            float4 a1 = *(float4*)&As[k][ty * 8 + 4];
            float4 b0 = *(float4*)&Bs[k][tx * 8];
            float4 b1 = *(float4*)&Bs[k][tx * 8 + 4];
            float ar[8] = {a0.x, a0.y, a0.z, a0.w, a1.x, a1.y, a1.z, a1.w};
            float br[8] = {b0.x, b0.y, b0.z, b0.w, b1.x, b1.y, b1.z, b1.w};
#pragma unroll
            for (int i = 0; i < 8; i++)
#pragma unroll
                for (int j = 0; j < 8; j++) acc[i][j] += ar[i] * br[j];
        }
        __syncthreads();
    }
#pragma unroll
    for (int i = 0; i < 8; i++) {
        int gr = row0 + ty * 8 + i;
        *(float4*)(g_S + gr * NU + col0 + tx * 8) =
            make_float4(acc[i][0], acc[i][1], acc[i][2], acc[i][3]);
        *(float4*)(g_S + gr * NU + col0 + tx * 8 + 4) =
            make_float4(acc[i][4], acc[i][5], acc[i][6], acc[i][7]);
    }
}

// out = sigmoid(S_s @ M + QC_s @ Bt^T) - 1000*F
__global__ __launch_bounds__(256) void final_kernel(const float* __restrict__ F,
                                                    float* __restrict__ out) {
    __shared__ float As[16][128];
    __shared__ float Bs[16][128];
    int tid = threadIdx.x;
    int tx = tid & 15, ty = tid >> 4;
    int row0 = blockIdx.y * 128, col0 = blockIdx.x * 128;
    float acc[8][8] = {};
    for (int kb = 0; kb < NU; kb += 16) {
#pragma unroll
        for (int l = 0; l < 2; l++) {
            int q = tid * 2 + l;
            int r = q >> 2, c = q & 3;
            float4 v = *(const float4*)(g_S + (row0 + r) * NU + kb + c * 4);
            As[c * 4 + 0][r] = v.x; As[c * 4 + 1][r] = v.y;
            As[c * 4 + 2][r] = v.z; As[c * 4 + 3][r] = v.w;
            int k2 = q >> 5, n = q & 31;
            *(float4*)&Bs[k2][n * 4] =
                *(const float4*)(g_M + (kb + k2) * NI + col0 + n * 4);
        }
        __syncthreads();
#pragma unroll
        for (int k = 0; k < 16; k++) {
            float4 a0 = *(float4*)&As[k][ty * 8];
            float4 a1 = *(float4*)&As[k][ty * 8 + 4];
            float4 b0 = *(float4*)&Bs[k][tx * 8];
            float4 b1 = *(float4*)&Bs[k][tx * 8 + 4];
            float ar[8] = {a0.x, a0.y, a0.z, a0.w, a1.x, a1.y, a1.z, a1.w};
            float br[8] = {b0.x, b0.y, b0.z, b0.w, b1.x, b1.y, b1.z, b1.w};
#pragma unroll
            for (int i = 0; i < 8; i++)
#pragma unroll
                for (int j = 0; j < 8; j++) acc[i][j] += ar[i] * br[j];
        }
        __syncthreads();
    }
    for (int kb = 0; kb < 64; kb += 16) {
#pragma unroll
        for (int l = 0; l < 2; l++) {
            int q = tid * 2 + l;
            int r = q >> 2, c = q & 3;
            float4 v = *(const float4*)(g_QC + (row0 + r) * NQ + kb + c * 4);
            As[c * 4 + 0][r] = v.x; As[c * 4 + 1][r] = v.y;
            As[c * 4 + 2][r] = v.z; As[c * 4 + 3][r] = v.w;
            float4 w = *(const float4*)(g_Bt + (col0 + r) * NQ + kb + c * 4);
            Bs[c * 4 + 0][r] = w.x; Bs[c * 4 + 1][r] = w.y;
            Bs[c * 4 + 2][r] = w.z; Bs[c * 4 + 3][r] = w.w;
        }
        __syncthreads();
#pragma unroll
        for (int k = 0; k < 16; k++) {
            float4 a0 = *(float4*)&As[k][ty * 8];
            float4 a1 = *(float4*)&As[k][ty * 8 + 4];
            float4 b0 = *(float4*)&Bs[k][tx * 8];
            float4 b1 = *(float4*)&Bs[k][tx * 8 + 4];
            float ar[8] = {a0.x, a0.y, a0.z, a0.w, a1.x, a1.y, a1.z, a1.w};
            float br[8] = {b0.x, b0.y, b0.z, b0.w, b1.x, b1.y, b1.z, b1.w};
#pragma unroll
            for (int i = 0; i < 8; i++)
#pragma unroll
                for (int j = 0; j < 8; j++) acc[i][j] += ar[i] * br[j];
        }
        __syncthreads();
    }
#pragma unroll
    for (int i = 0; i < 8; i++) {
        int gr = row0 + ty * 8 + i;
        int gc = col0 + tx * 8;
        float4 f0 = *(const float4*)(F + gr * NI + gc);
        float4 f1 = *(const float4*)(F + gr * NI + gc + 4);
        float4 o0, o1;
        o0.x = 1.0f / (1.0f + __expf(-acc[i][0])) - 1000.0f * f0.x;
        o0.y = 1.0f / (1.0f + __expf(-acc[i][1])) - 1000.0f * f0.y;
        o0.z = 1.0f / (1.0f + __expf(-acc[i][2])) - 1000.0f * f0.z;
        o0.w = 1.0f / (1.0f + __expf(-acc[i][3])) - 1000.0f * f0.w;
        o1.x = 1.0f / (1.0f + __expf(-acc[i][4])) - 1000.0f * f1.x;
        o1.y = 1.0f / (1.0f + __expf(-acc[i][5])) - 1000.0f * f1.y;
        o1.z = 1.0f / (1.0f + __expf(-acc[i][6])) - 1000.0f * f1.z;
        o1.w = 1.0f / (1.0f + __expf(-acc[i][7])) - 1000.0f * f1.w;
        *(float4*)(out + gr * NI + gc) = o0;
        *(float4*)(out + gr * NI + gc + 4) = o1;
    }
}

extern "C" void kernel_launch(void* const* d_in, const int* in_sizes, int n_in,
                              void* d_out, int out_size) {
    (void)in_sizes; (void)n_in; (void)out_size;
    const float* F = (const float*)d_in[0];
    float* out = (float*)d_out;

    float *pM, *pMt, *pQ, *pQ2, *pBt, *pQC, *pS, *pG, *pRinv, *pMinv;
    cudaGetSymbolAddress((void**)&pM, g_M);
    cudaGetSymbolAddress((void**)&pMt, g_Mt);
    cudaGetSymbolAddress((void**)&pQ, g_Q);
    cudaGetSymbolAddress((void**)&pQ2, g_Q2);
    cudaGetSymbolAddress((void**)&pBt, g_Bt);
    cudaGetSymbolAddress((void**)&pQC, g_QC);
    cudaGetSymbolAddress((void**)&pS, g_S);
    cudaGetSymbolAddress((void**)&pG, g_G);
    cudaGetSymbolAddress((void**)&pRinv, g_rinv);
    cudaGetSymbolAddress((void**)&pMinv, g_minv);

    // normalization + M/Mt
    rowsum_du_kernel<<<NU, 256>>>(F);
    colsum_di_kernel<<<NI / 256, 256>>>(F);
    build_M_kernel<<<dim3(NI / 32, NU / 32), dim3(32, 8)>>>(F);

    // S = M M^T (unscaled; used for subspace iteration AND 3-hop term)
    gemm_nt_S<<<dim3(NU / 128, NU / 128), 256>>>();

    // Q0 = Gaussian [NU, 64]
    rng_kernel<<<(NU * NQ) / 256, 256>>>(pQ);

    // subspace iteration in user space: Q <- cholQR(S @ Q)
    float* cur = pQ;
    float* nxt = pQ2;
    for (int it = 0; it < NITER; it++) {
        zero_kernel<<<(NU * NQ) / 256, 256>>>(nxt, NU * NQ);
        skinny_gemm<<<dim3(NU / 64, 8), 256>>>(nxt, pS, cur, NU, NU / 8);
        gram_part_kernel<<<NU / 128, 256>>>(nxt);
        chol_linv_kernel<<<1, 64>>>(NU / 128);
        trsm_apply_kernel<<<NU / 4, 256>>>(nxt);
        float* t = cur; cur = nxt; nxt = t;
    }
    // NITER even -> cur == pQ (qc_kernel reads g_Q)

    // Bt = M^T Q; G = Bt^T Bt; eigensolve -> C; QC = Q C
    zero_kernel<<<(NI * NQ) / 256, 256>>>(pBt, NI * NQ);
    skinny_gemm<<<dim3(NI / 64, 2), 256>>>(pBt, pMt, pQ, NU, NU / 2);
    zero_kernel<<<(NQ * NQ + 255) / 256, 256>>>(pG, NQ * NQ);
    gram_kernel<<<NI / 128, 256>>>(pBt);
    jacobi_kernel<<<1, 256>>>();
    qc_kernel<<<(NU * NQ) / 256, 256>>>();

    // rate row-sum inverse folded into QC rows
    colsum_bt_kernel<<<NQ, 256>>>();
    rsuminv_kernel<<<NU / 256, 256>>>();
    scale_rows_kernel<<<(NU * NQ) / 256, 256>>>(pQC, pRinv, NQ, NU * NQ);

    // fold 1/m3sum into S rows (after iterations are done with unscaled S)
    rowsum_M_kernel<<<NU, 256>>>();
    matvec_minv_kernel<<<NU, 256>>>();
    scale_rows_kernel<<<(NU * NU) / 256, 256>>>(pS, pMinv, NU, NU * NU);

    // fused final: out = sigmoid(S M + QC Bt^T) - 1000 F
    final_kernel<<<dim3(NI / 128, NU / 128), 256>>>(F, out);
}

// round 6
// speedup vs baseline: 3.2747x; 1.9461x over previous
#include <cuda_runtime.h>

#define NU 2048
#define NI 8192
#define NQ 64
#define NITER 10
#define NSWEEP 8

__device__ float g_M[NU * NI];
__device__ float g_Mt[NI * NU];
__device__ float g_S[NU * NU];
__device__ float g_Q[NU * NQ];
__device__ float g_Q2[NU * NQ];
__device__ float g_Bt[NI * NQ];
__device__ float g_QC[NU * NQ];
__device__ float g_G[NQ * NQ];
__device__ float g_Gp[16 * NQ * NQ];
__device__ float g_Li[NQ * NQ];
__device__ float g_C[NQ * NQ];
__device__ float g_du[NU];
__device__ float g_di[NI];
__device__ float g_mrow[NU];
__device__ float g_minv[NU];
__device__ float g_rinv[NU];
__device__ float g_bsum[NQ];

__global__ void zero_kernel(float* __restrict__ p, int n) {
    int i = blockIdx.x * 256 + threadIdx.x;
    if (i < n) p[i] = 0.0f;
}

__global__ void rowsum_du_kernel(const float* __restrict__ F) {
    __shared__ float red[256];
    int row = blockIdx.x, tid = threadIdx.x;
    float s = 0.0f;
    for (int j = tid; j < NI; j += 256) s += F[row * NI + j];
    red[tid] = s; __syncthreads();
    for (int off = 128; off > 0; off >>= 1) {
        if (tid < off) red[tid] += red[tid + off];
        __syncthreads();
    }
    if (tid == 0) g_du[row] = rsqrtf(red[0] + 1.0f);
}

__global__ void colsum_di_kernel(const float* __restrict__ F) {
    int j = blockIdx.x * 256 + threadIdx.x;
    float s = 0.0f;
    for (int i = 0; i < NU; i++) s += F[i * NI + j];
    g_di[j] = rsqrtf(s + 1.0f);
}

__global__ void build_M_kernel(const float* __restrict__ F) {
    __shared__ float sh[32][33];
    int tx = threadIdx.x, ty = threadIdx.y;
    int col0 = blockIdx.x * 32, row0 = blockIdx.y * 32;
    int j = col0 + tx;
    float dj = g_di[j];
#pragma unroll
    for (int k = 0; k < 4; k++) {
        int i = row0 + ty + k * 8;
        float v = g_du[i] * F[i * NI + j] * dj;
        g_M[i * NI + j] = v;
        sh[ty + k * 8][tx] = v;
    }
    __syncthreads();
#pragma unroll
    for (int k = 0; k < 4; k++) {
        int jj = col0 + ty + k * 8;
        g_Mt[jj * NU + row0 + tx] = sh[tx][ty + k * 8];
    }
}

__device__ __forceinline__ unsigned int hashu(unsigned int x) {
    x ^= x >> 16; x *= 0x7feb352dU; x ^= x >> 15; x *= 0x846ca68bU; x ^= x >> 16;
    return x;
}

__global__ void rng_kernel(float* __restrict__ p) {
    int gid = blockIdx.x * 256 + threadIdx.x;
    unsigned int h1 = hashu(2u * gid + 17u);
    unsigned int h2 = hashu(2u * gid + 18u);
    float u1 = ((h1 >> 9) + 0.5f) * (1.0f / 8388608.0f);
    float u2 = ((h2 >> 9) + 0.5f) * (1.0f / 8388608.0f);
    p[gid] = sqrtf(-2.0f * __logf(u1)) * __cosf(6.2831853f * u2);
}

// out[R,64] += A[R,K] @ W[K,64]; split-K over grid.y; out pre-zeroed.
__global__ __launch_bounds__(256) void skinny_gemm(
    float* __restrict__ out, const float* __restrict__ A,
    const float* __restrict__ W, int lda, int kchunk) {
    __shared__ float AsT[16][64];
    __shared__ float Ws[16][64];
    int tid = threadIdx.x;
    int tx = tid & 15, ty = tid >> 4;
    int row0 = blockIdx.x * 64;
    int kb0 = blockIdx.y * kchunk;
    int aR = tid >> 2, aC = tid & 3;
    int wK = tid >> 4, wQ = tid & 15;
    float acc[4][4] = {};
    for (int kb = kb0; kb < kb0 + kchunk; kb += 16) {
        float4 av = *(const float4*)(A + (row0 + aR) * lda + kb + aC * 4);
        AsT[aC * 4 + 0][aR] = av.x; AsT[aC * 4 + 1][aR] = av.y;
        AsT[aC * 4 + 2][aR] = av.z; AsT[aC * 4 + 3][aR] = av.w;
        *(float4*)(&Ws[wK][wQ * 4]) = *(const float4*)(W + (kb + wK) * NQ + wQ * 4);
        __syncthreads();
#pragma unroll
        for (int k = 0; k < 16; k++) {
            float4 a = *(float4*)&AsT[k][ty * 4];
            float4 w = *(float4*)&Ws[k][tx * 4];
            float aa[4] = {a.x, a.y, a.z, a.w};
            float ww[4] = {w.x, w.y, w.z, w.w};
#pragma unroll
            for (int i = 0; i < 4; i++)
#pragma unroll
                for (int j = 0; j < 4; j++) acc[i][j] += aa[i] * ww[j];
        }
        __syncthreads();
    }
#pragma unroll
    for (int i = 0; i < 4; i++)
#pragma unroll
        for (int j = 0; j < 4; j++)
            atomicAdd(&out[(row0 + ty * 4 + i) * NQ + tx * 4 + j], acc[i][j]);
}

// atomic Gram into g_G (used once, for Bt)
__global__ __launch_bounds__(256) void gram_kernel(const float* __restrict__ Y) {
    __shared__ float Ys[16][64];
    int tid = threadIdx.x;
    int tx = tid & 15, ty = tid >> 4;
    int wK = tid >> 4, wQ = tid & 15;
    int base = blockIdx.x * 128;
    float acc[4][4] = {};
    for (int c = 0; c < 8; c++) {
        *(float4*)&Ys[wK][wQ * 4] =
            *(const float4*)(Y + (base + c * 16 + wK) * NQ + wQ * 4);
        __syncthreads();
#pragma unroll
        for (int r = 0; r < 16; r++) {
            float4 a = *(float4*)&Ys[r][ty * 4];
            float4 b = *(float4*)&Ys[r][tx * 4];
            float aa[4] = {a.x, a.y, a.z, a.w};
            float bb[4] = {b.x, b.y, b.z, b.w};
#pragma unroll
            for (int i = 0; i < 4; i++)
#pragma unroll
                for (int j = 0; j < 4; j++) acc[i][j] += aa[i] * bb[j];
        }
        __syncthreads();
    }
#pragma unroll
    for (int i = 0; i < 4; i++)
#pragma unroll
        for (int j = 0; j < 4; j++)
            atomicAdd(&g_G[(ty * 4 + i) * NQ + tx * 4 + j], acc[i][j]);
}

// per-block Gram partials (no atomics) for the QR loop
__global__ __launch_bounds__(256) void gram_part_kernel(const float* __restrict__ Y) {
    __shared__ float Ys[16][64];
    int tid = threadIdx.x;
    int tx = tid & 15, ty = tid >> 4;
    int wK = tid >> 4, wQ = tid & 15;
    int base = blockIdx.x * 128;
    float acc[4][4] = {};
    for (int c = 0; c < 8; c++) {
        *(float4*)&Ys[wK][wQ * 4] =
            *(const float4*)(Y + (base + c * 16 + wK) * NQ + wQ * 4);
        __syncthreads();
#pragma unroll
        for (int r = 0; r < 16; r++) {
            float4 a = *(float4*)&Ys[r][ty * 4];
            float4 b = *(float4*)&Ys[r][tx * 4];
            float aa[4] = {a.x, a.y, a.z, a.w};
            float bb[4] = {b.x, b.y, b.z, b.w};
#pragma unroll
            for (int i = 0; i < 4; i++)
#pragma unroll
                for (int j = 0; j < 4; j++) acc[i][j] += aa[i] * bb[j];
        }
        __syncthreads();
    }
    float* dst = g_Gp + blockIdx.x * (NQ * NQ);
#pragma unroll
    for (int i = 0; i < 4; i++)
#pragma unroll
        for (int j = 0; j < 4; j++)
            dst[(ty * 4 + i) * NQ + tx * 4 + j] = acc[i][j];
}

// sum Gram partials -> Cholesky L -> explicit Linv (lower), no local spills.
__global__ void chol_linv_kernel(int nparts) {
    __shared__ float sA[64][65];
    __shared__ float sX[64][65];
    int tid = threadIdx.x;
    for (int j = 0; j < 64; j++) {
        float s = 0.0f;
        for (int p = 0; p < nparts; p++) s += g_Gp[p * 4096 + tid * 64 + j];
        sA[tid][j] = s;
    }
    __syncthreads();
    for (int k = 0; k < 64; k++) {
        if (tid == k) sA[k][k] = sqrtf(fmaxf(sA[k][k], 1e-30f));
        __syncthreads();
        if (tid > k) sA[tid][k] /= sA[k][k];
        __syncthreads();
        if (tid > k)
            for (int j = k + 1; j <= tid; j++)
                sA[tid][j] -= sA[tid][k] * sA[j][k];
        __syncthreads();
    }
    // column-parallel forward solve: thread c computes Linv[:,c] (sync-free)
    int c = tid;
    for (int i = c; i < 64; i++) {
        float acc = (i == c) ? 1.0f : 0.0f;
        for (int k = c; k < i; k++) acc -= sA[i][k] * sX[k][c];
        float v = acc / sA[i][i];
        sX[i][c] = v;
        g_Li[i * 64 + c] = v;
    }
}

// Y <- Y * Linv^T ; 4 rows/block
__global__ __launch_bounds__(256) void trsm_apply_kernel(float* __restrict__ Y) {
    __shared__ float sLi[64][65];
    __shared__ float sY[4][64];
    int tid = threadIdx.x;
    for (int i = tid; i < 4096; i += 256) sLi[i >> 6][i & 63] = g_Li[i];
    int lr = tid >> 6, j = tid & 63;
    int r = blockIdx.x * 4 + lr;
    sY[lr][j] = Y[r * NQ + j];
    __syncthreads();
    float acc = 0.0f;
    for (int k = 0; k <= j; k++) acc += sY[lr][k] * sLi[j][k];
    Y[r * NQ + j] = acc;
}

// Jacobi eigensolve of g_G; g_C = V diag(lam^1.5/lammax^2) V^T
__global__ __launch_bounds__(256) void jacobi_kernel() {
    __shared__ float sA[64][65];
    __shared__ float sV[64][65];
    __shared__ float pc[32], ps[32];
    __shared__ int pp[32], pq[32];
    __shared__ float lam[64];
    __shared__ float smax;
    int tid = threadIdx.x;
    for (int o = tid; o < 4096; o += 256) {
        int r = o >> 6, c = o & 63;
        sA[r][c] = g_G[o];
        sV[r][c] = (r == c) ? 1.0f : 0.0f;
    }
    __syncthreads();
    for (int sweep = 0; sweep < NSWEEP; sweep++) {
        for (int r = 0; r < 63; r++) {
            if (tid < 32) {
                int p, q;
                if (tid == 0) { p = 63; q = r; }
                else { p = (r + tid) % 63; q = (r - tid + 63) % 63; }
                float app = sA[p][p], aqq = sA[q][q], apq = sA[p][q];
                float c = 1.0f, s = 0.0f;
                if (fabsf(apq) > 1e-20f) {
                    float tau = (aqq - app) / (2.0f * apq);
                    float t = ((tau >= 0.0f) ? 1.0f : -1.0f) /
                              (fabsf(tau) + sqrtf(1.0f + tau * tau));
                    c = rsqrtf(1.0f + t * t);
                    s = t * c;
                }
                pp[tid] = p; pq[tid] = q; pc[tid] = c; ps[tid] = s;
            }
            __syncthreads();
            for (int it = tid; it < 4096; it += 256) {
                int pr = it >> 7;
                int rest = it & 127;
                int i = rest & 63;
                float c = pc[pr], s = ps[pr];
                int p = pp[pr], q = pq[pr];
                if (rest < 64) {
                    float x = sA[i][p], y = sA[i][q];
                    sA[i][p] = c * x - s * y;
                    sA[i][q] = s * x + c * y;
                } else {
                    float x = sV[i][p], y = sV[i][q];
                    sV[i][p] = c * x - s * y;
                    sV[i][q] = s * x + c * y;
                }
            }
            __syncthreads();
            for (int it = tid; it < 2048; it += 256) {
                int pr = it >> 6;
                int j = it & 63;
                float c = pc[pr], s = ps[pr];
                int p = pp[pr], q = pq[pr];
                float x = sA[p][j], y = sA[q][j];
                sA[p][j] = c * x - s * y;
                sA[q][j] = s * x + c * y;
            }
            __syncthreads();
        }
    }
    if (tid < 64) lam[tid] = fmaxf(sA[tid][tid], 0.0f);
    __syncthreads();
    if (tid == 0) {
        float m = 0.0f;
        for (int k = 0; k < 64; k++) m = fmaxf(m, lam[k]);
        smax = m;
    }
    __syncthreads();
    if (tid < 64) {
        float l = lam[tid];
        lam[tid] = l * sqrtf(l) / (smax * smax);
    }
    __syncthreads();
    for (int o = tid; o < 4096; o += 256) {
        int i = o >> 6, j = o & 63;
        float acc = 0.0f;
        for (int k = 0; k < 64; k++) acc += sV[i][k] * lam[k] * sV[j][k];
        g_C[o] = acc;
    }
}

__global__ __launch_bounds__(256) void qc_kernel() {
    __shared__ float sC[64 * 64];
    int tid = threadIdx.x;
    for (int i = tid; i < 4096; i += 256) sC[i] = g_C[i];
    __syncthreads();
    int gid = blockIdx.x * 256 + tid;
    int i = gid >> 6, k2 = gid & 63;
    float acc = 0.0f;
    for (int k = 0; k < 64; k++) acc += g_Q[i * 64 + k] * sC[k * 64 + k2];
    g_QC[gid] = acc;
}

__global__ void colsum_bt_kernel() {
    __shared__ float red[256];
    int b = blockIdx.x, tid = threadIdx.x;
    float s = 0.0f;
    for (int r = tid; r < NI; r += 256) s += g_Bt[r * NQ + b];
    red[tid] = s; __syncthreads();
    for (int off = 128; off > 0; off >>= 1) {
        if (tid < off) red[tid] += red[tid + off];
        __syncthreads();
    }
    if (tid == 0) g_bsum[b] = red[0];
}

__global__ void rsuminv_kernel() {
    int gid = blockIdx.x * 256 + threadIdx.x;
    float acc = 0.0f;
    for (int k = 0; k < 64; k++) acc += g_QC[gid * 64 + k] * g_bsum[k];
    g_rinv[gid] = 1.0f / acc;
}

__global__ void rowsum_M_kernel() {
    __shared__ float red[256];
    int row = blockIdx.x, tid = threadIdx.x;
    float s = 0.0f;
    for (int j = tid; j < NI; j += 256) s += g_M[row * NI + j];
    red[tid] = s; __syncthreads();
    for (int off = 128; off > 0; off >>= 1) {
        if (tid < off) red[tid] += red[tid + off];
        __syncthreads();
    }
    if (tid == 0) g_mrow[row] = red[0];
}

__global__ void matvec_minv_kernel() {
    __shared__ float red[256];
    int row = blockIdx.x, tid = threadIdx.x;
    float s = 0.0f;
    for (int j = tid; j < NU; j += 256) s += g_S[row * NU + j] * g_mrow[j];
    red[tid] = s; __syncthreads();
    for (int off = 128; off > 0; off >>= 1) {
        if (tid < off) red[tid] += red[tid + off];
        __syncthreads();
    }
    if (tid == 0) g_minv[row] = 1.0f / red[0];
}

__global__ void scale_rows_kernel(float* __restrict__ p, const float* __restrict__ v,
                                  int cols, int n) {
    int gid = blockIdx.x * 256 + threadIdx.x;
    if (gid < n) p[gid] *= v[gid / cols];
}

// S = M M^T, upper-triangular 128x128 blocks only (136 blocks), conflict-fixed mapping
__global__ __launch_bounds__(256) void gemm_nt_S() {
    __shared__ float As[16][128];
    __shared__ float Bs[16][128];
    int tid = threadIdx.x;
    int tx = tid & 15, ty = tid >> 4;
    // decode upper-tri block index
    int bid = blockIdx.x, by = 0, rem = bid;
#pragma unroll
    for (int t = 0; t < 16; t++) {
        if (rem >= 16 - by) { rem -= 16 - by; by++; }
    }
    int bx = by + rem;
    int row0 = by * 128, col0 = bx * 128;
    float acc[8][8] = {};
    for (int kb = 0; kb < NI; kb += 16) {
#pragma unroll
        for (int l = 0; l < 2; l++) {
            int q = tid * 2 + l;
            int r = q >> 2, c = q & 3;
            float4 v = *(const float4*)(g_M + (row0 + r) * NI + kb + c * 4);
            As[c * 4 + 0][r] = v.x; As[c * 4 + 1][r] = v.y;
            As[c * 4 + 2][r] = v.z; As[c * 4 + 3][r] = v.w;
            float4 w = *(const float4*)(g_M + (col0 + r) * NI + kb + c * 4);
            Bs[c * 4 + 0][r] = w.x; Bs[c * 4 + 1][r] = w.y;
            Bs[c * 4 + 2][r] = w.z; Bs[c * 4 + 3][r] = w.w;
        }
        __syncthreads();
#pragma unroll
        for (int k = 0; k < 16; k++) {
            float4 a0 = *(float4*)&As[k][ty * 8];
            float4 a1 = *(float4*)&As[k][ty * 8 + 4];
            float4 b0 = *(float4*)&Bs[k][tx * 4];
            float4 b1 = *(float4*)&Bs[k][64 + tx * 4];
            float ar[8] = {a0.x, a0.y, a0.z, a0.w, a1.x, a1.y, a1.z, a1.w};
            float br[8] = {b0.x, b0.y, b0.z, b0.w, b1.x, b1.y, b1.z, b1.w};
#pragma unroll
            for (int i = 0; i < 8; i++)
#pragma unroll
                for (int j = 0; j < 8; j++) acc[i][j] += ar[i] * br[j];
        }
        __syncthreads();
    }
#pragma unroll
    for (int i = 0; i < 8; i++) {
        int gr = row0 + ty * 8 + i;
        *(float4*)(g_S + gr * NU + col0 + tx * 4) =
            make_float4(acc[i][0], acc[i][1], acc[i][2], acc[i][3]);
        *(float4*)(g_S + gr * NU + col0 + 64 + tx * 4) =
            make_float4(acc[i][4], acc[i][5], acc[i][6], acc[i][7]);
    }
}

// mirror lower triangle of S from upper (32x32 tiles)
__global__ void mirror_S_kernel() {
    __shared__ float sh[32][33];
    int tr = blockIdx.y, tc = blockIdx.x;
    if (tr <= tc) return;
    int tx = threadIdx.x, ty = threadIdx.y;
#pragma unroll
    for (int k = 0; k < 4; k++)
        sh[ty + k * 8][tx] = g_S[(tc * 32 + ty + k * 8) * NU + tr * 32 + tx];
    __syncthreads();
#pragma unroll
    for (int k = 0; k < 4; k++)
        g_S[(tr * 32 + ty + k * 8) * NU + tc * 32 + tx] = sh[tx][ty + k * 8];
}

// out = sigmoid(minv[row]*(S @ M) + QC_s @ Bt^T) - 1000*F
__global__ __launch_bounds__(256) void final_kernel(const float* __restrict__ F,
                                                    float* __restrict__ out) {
    __shared__ float As[16][128];
    __shared__ float Bs[16][128];
    int tid = threadIdx.x;
    int tx = tid & 15, ty = tid >> 4;
    int row0 = blockIdx.y * 128, col0 = blockIdx.x * 128;
    float acc[8][8] = {};
    for (int kb = 0; kb < NU; kb += 16) {
#pragma unroll
        for (int l = 0; l < 2; l++) {
            int q = tid * 2 + l;
            int r = q >> 2, c = q & 3;
            float4 v = *(const float4*)(g_S + (row0 + r) * NU + kb + c * 4);
            As[c * 4 + 0][r] = v.x; As[c * 4 + 1][r] = v.y;
            As[c * 4 + 2][r] = v.z; As[c * 4 + 3][r] = v.w;
            int k2 = q >> 5, n = q & 31;
            *(float4*)&Bs[k2][n * 4] =
                *(const float4*)(g_M + (kb + k2) * NI + col0 + n * 4);
        }
        __syncthreads();
#pragma unroll
        for (int k = 0; k < 16; k++) {
            float4 a0 = *(float4*)&As[k][ty * 8];
            float4 a1 = *(float4*)&As[k][ty * 8 + 4];
            float4 b0 = *(float4*)&Bs[k][tx * 4];
            float4 b1 = *(float4*)&Bs[k][64 + tx * 4];
            float ar[8] = {a0.x, a0.y, a0.z, a0.w, a1.x, a1.y, a1.z, a1.w};
            float br[8] = {b0.x, b0.y, b0.z, b0.w, b1.x, b1.y, b1.z, b1.w};
#pragma unroll
            for (int i = 0; i < 8; i++)
#pragma unroll
                for (int j = 0; j < 8; j++) acc[i][j] += ar[i] * br[j];
        }
        __syncthreads();
    }
    // scale S-part by minv[row]
#pragma unroll
    for (int i = 0; i < 8; i++) {
        float mv = g_minv[row0 + ty * 8 + i];
#pragma unroll
        for (int j = 0; j < 8; j++) acc[i][j] *= mv;
    }
    for (int kb = 0; kb < 64; kb += 16) {
#pragma unroll
        for (int l = 0; l < 2; l++) {
            int q = tid * 2 + l;
            int r = q >> 2, c = q & 3;
            float4 v = *(const float4*)(g_QC + (row0 + r) * NQ + kb + c * 4);
            As[c * 4 + 0][r] = v.x; As[c * 4 + 1][r] = v.y;
            As[c * 4 + 2][r] = v.z; As[c * 4 + 3][r] = v.w;
            float4 w = *(const float4*)(g_Bt + (col0 + r) * NQ + kb + c * 4);
            Bs[c * 4 + 0][r] = w.x; Bs[c * 4 + 1][r] = w.y;
            Bs[c * 4 + 2][r] = w.z; Bs[c * 4 + 3][r] = w.w;
        }
        __syncthreads();
#pragma unroll
        for (int k = 0; k < 16; k++) {
            float4 a0 = *(float4*)&As[k][ty * 8];
            float4 a1 = *(float4*)&As[k][ty * 8 + 4];
            float4 b0 = *(float4*)&Bs[k][tx * 4];
            float4 b1 = *(float4*)&Bs[k][64 + tx * 4];
            float ar[8] = {a0.x, a0.y, a0.z, a0.w, a1.x, a1.y, a1.z, a1.w};
            float br[8] = {b0.x, b0.y, b0.z, b0.w, b1.x, b1.y, b1.z, b1.w};
#pragma unroll
            for (int i = 0; i < 8; i++)
#pragma unroll
                for (int j = 0; j < 8; j++) acc[i][j] += ar[i] * br[j];
        }
        __syncthreads();
    }
#pragma unroll
    for (int i = 0; i < 8; i++) {
        int gr = row0 + ty * 8 + i;
        int gc0 = col0 + tx * 4;
        int gc1 = col0 + 64 + tx * 4;
        float4 f0 = *(const float4*)(F + gr * NI + gc0);
        float4 f1 = *(const float4*)(F + gr * NI + gc1);
        float4 o0, o1;
        o0.x = 1.0f / (1.0f + __expf(-acc[i][0])) - 1000.0f * f0.x;
        o0.y = 1.0f / (1.0f + __expf(-acc[i][1])) - 1000.0f * f0.y;
        o0.z = 1.0f / (1.0f + __expf(-acc[i][2])) - 1000.0f * f0.z;
        o0.w = 1.0f / (1.0f + __expf(-acc[i][3])) - 1000.0f * f0.w;
        o1.x = 1.0f / (1.0f + __expf(-acc[i][4])) - 1000.0f * f1.x;
        o1.y = 1.0f / (1.0f + __expf(-acc[i][5])) - 1000.0f * f1.y;
        o1.z = 1.0f / (1.0f + __expf(-acc[i][6])) - 1000.0f * f1.z;
        o1.w = 1.0f / (1.0f + __expf(-acc[i][7])) - 1000.0f * f1.w;
        *(float4*)(out + gr * NI + gc0) = o0;
        *(float4*)(out + gr * NI + gc1) = o1;
    }
}

extern "C" void kernel_launch(void* const* d_in, const int* in_sizes, int n_in,
                              void* d_out, int out_size) {
    (void)in_sizes; (void)n_in; (void)out_size;
    const float* F = (const float*)d_in[0];
    float* out = (float*)d_out;

    float *pM, *pMt, *pQ, *pQ2, *pBt, *pQC, *pS, *pG, *pRinv;
    cudaGetSymbolAddress((void**)&pM, g_M);
    cudaGetSymbolAddress((void**)&pMt, g_Mt);
    cudaGetSymbolAddress((void**)&pQ, g_Q);
    cudaGetSymbolAddress((void**)&pQ2, g_Q2);
    cudaGetSymbolAddress((void**)&pBt, g_Bt);
    cudaGetSymbolAddress((void**)&pQC, g_QC);
    cudaGetSymbolAddress((void**)&pS, g_S);
    cudaGetSymbolAddress((void**)&pG, g_G);
    cudaGetSymbolAddress((void**)&pRinv, g_rinv);

    // normalization + M/Mt
    rowsum_du_kernel<<<NU, 256>>>(F);
    colsum_di_kernel<<<NI / 256, 256>>>(F);
    build_M_kernel<<<dim3(NI / 32, NU / 32), dim3(32, 8)>>>(F);

    // S = M M^T (upper blocks + mirror)
    gemm_nt_S<<<136, 256>>>();
    mirror_S_kernel<<<dim3(NU / 32, NU / 32), dim3(32, 8)>>>();

    // Q0 = Gaussian [NU, 64]
    rng_kernel<<<(NU * NQ) / 256, 256>>>(pQ);

    // subspace iteration: Q <- cholQR(S @ Q)
    float* cur = pQ;
    float* nxt = pQ2;
    for (int it = 0; it < NITER; it++) {
        zero_kernel<<<(NU * NQ) / 256, 256>>>(nxt, NU * NQ);
        skinny_gemm<<<dim3(NU / 64, 8), 256>>>(nxt, pS, cur, NU, NU / 8);
        gram_part_kernel<<<NU / 128, 256>>>(nxt);
        chol_linv_kernel<<<1, 64>>>(NU / 128);
        trsm_apply_kernel<<<NU / 4, 256>>>(nxt);
        float* t = cur; cur = nxt; nxt = t;
    }
    // NITER even -> cur == pQ

    // Bt = M^T Q; G = Bt^T Bt; eigensolve -> C; QC = Q C
    zero_kernel<<<(NI * NQ) / 256, 256>>>(pBt, NI * NQ);
    skinny_gemm<<<dim3(NI / 64, 2), 256>>>(pBt, pMt, pQ, NU, NU / 2);
    zero_kernel<<<(NQ * NQ + 255) / 256, 256>>>(pG, NQ * NQ);
    gram_kernel<<<NI / 128, 256>>>(pBt);
    jacobi_kernel<<<1, 256>>>();
    qc_kernel<<<(NU * NQ) / 256, 256>>>();

    // rate row-sum inverse folded into QC rows
    colsum_bt_kernel<<<NQ, 256>>>();
    rsuminv_kernel<<<NU / 256, 256>>>();
    scale_rows_kernel<<<(NU * NQ) / 256, 256>>>(pQC, pRinv, NQ, NU * NQ);

    // m3 row-sum inverse (applied in final epilogue)
    rowsum_M_kernel<<<NU, 256>>>();
    matvec_minv_kernel<<<NU, 256>>>();

    // fused final: out = sigmoid(minv*(S M) + QC Bt^T) - 1000 F
    final_kernel<<<dim3(NI / 128, NU / 128), 256>>>(F, out);
}

// round 8
// speedup vs baseline: 4.9627x; 1.5155x over previous
#include <cuda_runtime.h>
#include <cuda_bf16.h>
#include <mma.h>
#include <cstdint>

using namespace nvcuda;

#define NU 2048
#define NI 8192
#define NQ 64
#define NITER 10
#define NSWEEP 8

// ---------------- device globals ----------------
__device__ float g_M[NU * NI];
__device__ float g_Mt[NI * NU];
__device__ float g_S[NU * NU];
__device__ __nv_bfloat16 g_Mbf[NU * NI];
__device__ __nv_bfloat16 g_Mtbf[NI * NU];
__device__ __nv_bfloat16 g_Sbf[NU * NU];
__device__ __nv_bfloat16 g_QCbf[NU * NQ];
__device__ __nv_bfloat16 g_Btbf[NI * NQ];
__device__ float g_Q[NU * NQ];
__device__ float g_Q2[NU * NQ];
__device__ float g_Bt[NI * NQ];
__device__ float g_QC[NU * NQ];
__device__ float g_G[NQ * NQ];
__device__ float g_Gp[16 * NQ * NQ];
__device__ float g_Li[NQ * NQ];
__device__ float g_C[NQ * NQ];
__device__ float g_du[NU];
__device__ float g_di[NI];
__device__ float g_mrow[NU];
__device__ float g_minv[NU];
__device__ float g_rinv[NU];
__device__ float g_bsum[NQ];

// ---------------- small helpers ----------------
__global__ void zero_kernel(float* __restrict__ p, int n) {
    int i = blockIdx.x * 256 + threadIdx.x;
    if (i < n) p[i] = 0.0f;
}

__global__ void rowsum_du_kernel(const float* __restrict__ F) {
    __shared__ float red[256];
    int row = blockIdx.x, tid = threadIdx.x;
    float s = 0.0f;
    for (int j = tid; j < NI; j += 256) s += F[row * NI + j];
    red[tid] = s; __syncthreads();
    for (int off = 128; off > 0; off >>= 1) {
        if (tid < off) red[tid] += red[tid + off];
        __syncthreads();
    }
    if (tid == 0) g_du[row] = rsqrtf(red[0] + 1.0f);
}

__global__ void colsum_di_kernel(const float* __restrict__ F) {
    int j = blockIdx.x * 256 + threadIdx.x;
    float s = 0.0f;
    for (int i = 0; i < NU; i++) s += F[i * NI + j];
    g_di[j] = rsqrtf(s + 1.0f);
}

__global__ void build_M_kernel(const float* __restrict__ F) {
    __shared__ float sh[32][33];
    int tx = threadIdx.x, ty = threadIdx.y;
    int col0 = blockIdx.x * 32, row0 = blockIdx.y * 32;
    int j = col0 + tx;
    float dj = g_di[j];
#pragma unroll
    for (int k = 0; k < 4; k++) {
        int i = row0 + ty + k * 8;
        float v = g_du[i] * F[i * NI + j] * dj;
        g_M[i * NI + j] = v;
        g_Mbf[i * NI + j] = __float2bfloat16(v);
        sh[ty + k * 8][tx] = v;
    }
    __syncthreads();
#pragma unroll
    for (int k = 0; k < 4; k++) {
        int jj = col0 + ty + k * 8;
        float v = sh[tx][ty + k * 8];
        g_Mt[jj * NU + row0 + tx] = v;
        g_Mtbf[jj * NU + row0 + tx] = __float2bfloat16(v);
    }
}

__device__ __forceinline__ unsigned int hashu(unsigned int x) {
    x ^= x >> 16; x *= 0x7feb352dU; x ^= x >> 15; x *= 0x846ca68bU; x ^= x >> 16;
    return x;
}

__global__ void rng_kernel(float* __restrict__ p) {
    int gid = blockIdx.x * 256 + threadIdx.x;
    unsigned int h1 = hashu(2u * gid + 17u);
    unsigned int h2 = hashu(2u * gid + 18u);
    float u1 = ((h1 >> 9) + 0.5f) * (1.0f / 8388608.0f);
    float u2 = ((h2 >> 9) + 0.5f) * (1.0f / 8388608.0f);
    p[gid] = sqrtf(-2.0f * __logf(u1)) * __cosf(6.2831853f * u2);
}

// out[R,64] += A[R,K] @ W[K,64]; split-K over grid.y; out pre-zeroed.
__global__ __launch_bounds__(256) void skinny_gemm(
    float* __restrict__ out, const float* __restrict__ A,
    const float* __restrict__ W, int lda, int kchunk) {
    __shared__ float AsT[16][64];
    __shared__ float Ws[16][64];
    int tid = threadIdx.x;
    int tx = tid & 15, ty = tid >> 4;
    int row0 = blockIdx.x * 64;
    int kb0 = blockIdx.y * kchunk;
    int aR = tid >> 2, aC = tid & 3;
    int wK = tid >> 4, wQ = tid & 15;
    float acc[4][4] = {};
    for (int kb = kb0; kb < kb0 + kchunk; kb += 16) {
        float4 av = *(const float4*)(A + (size_t)(row0 + aR) * lda + kb + aC * 4);
        AsT[aC * 4 + 0][aR] = av.x; AsT[aC * 4 + 1][aR] = av.y;
        AsT[aC * 4 + 2][aR] = av.z; AsT[aC * 4 + 3][aR] = av.w;
        *(float4*)(&Ws[wK][wQ * 4]) = *(const float4*)(W + (kb + wK) * NQ + wQ * 4);
        __syncthreads();
#pragma unroll
        for (int k = 0; k < 16; k++) {
            float4 a = *(float4*)&AsT[k][ty * 4];
            float4 w = *(float4*)&Ws[k][tx * 4];
            float aa[4] = {a.x, a.y, a.z, a.w};
            float ww[4] = {w.x, w.y, w.z, w.w};
#pragma unroll
            for (int i = 0; i < 4; i++)
#pragma unroll
                for (int j = 0; j < 4; j++) acc[i][j] += aa[i] * ww[j];
        }
        __syncthreads();
    }
#pragma unroll
    for (int i = 0; i < 4; i++)
#pragma unroll
        for (int j = 0; j < 4; j++)
            atomicAdd(&out[(row0 + ty * 4 + i) * NQ + tx * 4 + j], acc[i][j]);
}

__global__ __launch_bounds__(256) void gram_kernel(const float* __restrict__ Y) {
    __shared__ float Ys[16][64];
    int tid = threadIdx.x;
    int tx = tid & 15, ty = tid >> 4;
    int wK = tid >> 4, wQ = tid & 15;
    int base = blockIdx.x * 128;
    float acc[4][4] = {};
    for (int c = 0; c < 8; c++) {
        *(float4*)&Ys[wK][wQ * 4] =
            *(const float4*)(Y + (base + c * 16 + wK) * NQ + wQ * 4);
        __syncthreads();
#pragma unroll
        for (int r = 0; r < 16; r++) {
            float4 a = *(float4*)&Ys[r][ty * 4];
            float4 b = *(float4*)&Ys[r][tx * 4];
            float aa[4] = {a.x, a.y, a.z, a.w};
            float bb[4] = {b.x, b.y, b.z, b.w};
#pragma unroll
            for (int i = 0; i < 4; i++)
#pragma unroll
                for (int j = 0; j < 4; j++) acc[i][j] += aa[i] * bb[j];
        }
        __syncthreads();
    }
#pragma unroll
    for (int i = 0; i < 4; i++)
#pragma unroll
        for (int j = 0; j < 4; j++)
            atomicAdd(&g_G[(ty * 4 + i) * NQ + tx * 4 + j], acc[i][j]);
}

__global__ __launch_bounds__(256) void gram_part_kernel(const float* __restrict__ Y) {
    __shared__ float Ys[16][64];
    int tid = threadIdx.x;
    int tx = tid & 15, ty = tid >> 4;
    int wK = tid >> 4, wQ = tid & 15;
    int base = blockIdx.x * 128;
    float acc[4][4] = {};
    for (int c = 0; c < 8; c++) {
        *(float4*)&Ys[wK][wQ * 4] =
            *(const float4*)(Y + (base + c * 16 + wK) * NQ + wQ * 4);
        __syncthreads();
#pragma unroll
        for (int r = 0; r < 16; r++) {
            float4 a = *(float4*)&Ys[r][ty * 4];
            float4 b = *(float4*)&Ys[r][tx * 4];
            float aa[4] = {a.x, a.y, a.z, a.w};
            float bb[4] = {b.x, b.y, b.z, b.w};
#pragma unroll
            for (int i = 0; i < 4; i++)
#pragma unroll
                for (int j = 0; j < 4; j++) acc[i][j] += aa[i] * bb[j];
        }
        __syncthreads();
    }
    float* dst = g_Gp + blockIdx.x * (NQ * NQ);
#pragma unroll
    for (int i = 0; i < 4; i++)
#pragma unroll
        for (int j = 0; j < 4; j++)
            dst[(ty * 4 + i) * NQ + tx * 4 + j] = acc[i][j];
}

__global__ void chol_linv_kernel(int nparts) {
    __shared__ float sA[64][65];
    __shared__ float sX[64][65];
    int tid = threadIdx.x;
    for (int j = 0; j < 64; j++) {
        float s = 0.0f;
        for (int p = 0; p < nparts; p++) s += g_Gp[p * 4096 + tid * 64 + j];
        sA[tid][j] = s;
    }
    __syncthreads();
    for (int k = 0; k < 64; k++) {
        if (tid == k) sA[k][k] = sqrtf(fmaxf(sA[k][k], 1e-30f));
        __syncthreads();
        if (tid > k) sA[tid][k] /= sA[k][k];
        __syncthreads();
        if (tid > k)
            for (int j = k + 1; j <= tid; j++)
                sA[tid][j] -= sA[tid][k] * sA[j][k];
        __syncthreads();
    }
    int c = tid;
    for (int i = c; i < 64; i++) {
        float acc = (i == c) ? 1.0f : 0.0f;
        for (int k = c; k < i; k++) acc -= sA[i][k] * sX[k][c];
        float v = acc / sA[i][i];
        sX[i][c] = v;
        g_Li[i * 64 + c] = v;
    }
}

__global__ __launch_bounds__(256) void trsm_apply_kernel(float* __restrict__ Y) {
    __shared__ float sLi[64][65];
    __shared__ float sY[4][64];
    int tid = threadIdx.x;
    for (int i = tid; i < 4096; i += 256) sLi[i >> 6][i & 63] = g_Li[i];
    int lr = tid >> 6, j = tid & 63;
    int r = blockIdx.x * 4 + lr;
    sY[lr][j] = Y[r * NQ + j];
    __syncthreads();
    float acc = 0.0f;
    for (int k = 0; k <= j; k++) acc += sY[lr][k] * sLi[j][k];
    Y[r * NQ + j] = acc;
}

__global__ __launch_bounds__(256) void jacobi_kernel() {
    __shared__ float sA[64][65];
    __shared__ float sV[64][65];
    __shared__ float pc[32], ps[32];
    __shared__ int pp[32], pq[32];
    __shared__ float lam[64];
    __shared__ float smax;
    int tid = threadIdx.x;
    for (int o = tid; o < 4096; o += 256) {
        int r = o >> 6, c = o & 63;
        sA[r][c] = g_G[o];
        sV[r][c] = (r == c) ? 1.0f : 0.0f;
    }
    __syncthreads();
    for (int sweep = 0; sweep < NSWEEP; sweep++) {
        for (int r = 0; r < 63; r++) {
            if (tid < 32) {
                int p, q;
                if (tid == 0) { p = 63; q = r; }
                else { p = (r + tid) % 63; q = (r - tid + 63) % 63; }
                float app = sA[p][p], aqq = sA[q][q], apq = sA[p][q];
                float c = 1.0f, s = 0.0f;
                if (fabsf(apq) > 1e-20f) {
                    float tau = (aqq - app) / (2.0f * apq);
                    float t = ((tau >= 0.0f) ? 1.0f : -1.0f) /
                              (fabsf(tau) + sqrtf(1.0f + tau * tau));
                    c = rsqrtf(1.0f + t * t);
                    s = t * c;
                }
                pp[tid] = p; pq[tid] = q; pc[tid] = c; ps[tid] = s;
            }
            __syncthreads();
            for (int it = tid; it < 4096; it += 256) {
                int pr = it >> 7;
                int rest = it & 127;
                int i = rest & 63;
                float c = pc[pr], s = ps[pr];
                int p = pp[pr], q = pq[pr];
                if (rest < 64) {
                    float x = sA[i][p], y = sA[i][q];
                    sA[i][p] = c * x - s * y;
                    sA[i][q] = s * x + c * y;
                } else {
                    float x = sV[i][p], y = sV[i][q];
                    sV[i][p] = c * x - s * y;
                    sV[i][q] = s * x + c * y;
                }
            }
            __syncthreads();
            for (int it = tid; it < 2048; it += 256) {
                int pr = it >> 6;
                int j = it & 63;
                float c = pc[pr], s = ps[pr];
                int p = pp[pr], q = pq[pr];
                float x = sA[p][j], y = sA[q][j];
                sA[p][j] = c * x - s * y;
                sA[q][j] = s * x + c * y;
            }
            __syncthreads();
        }
    }
    if (tid < 64) lam[tid] = fmaxf(sA[tid][tid], 0.0f);
    __syncthreads();
    if (tid == 0) {
        float m = 0.0f;
        for (int k = 0; k < 64; k++) m = fmaxf(m, lam[k]);
        smax = m;
    }
    __syncthreads();
    if (tid < 64) {
        float l = lam[tid];
        lam[tid] = l * sqrtf(l) / (smax * smax);
    }
    __syncthreads();
    for (int o = tid; o < 4096; o += 256) {
        int i = o >> 6, j = o & 63;
        float acc = 0.0f;
        for (int k = 0; k < 64; k++) acc += sV[i][k] * lam[k] * sV[j][k];
        g_C[o] = acc;
    }
}

__global__ __launch_bounds__(256) void qc_kernel() {
    __shared__ float sC[64 * 64];
    int tid = threadIdx.x;
    for (int i = tid; i < 4096; i += 256) sC[i] = g_C[i];
    __syncthreads();
    int gid = blockIdx.x * 256 + tid;
    int i = gid >> 6, k2 = gid & 63;
    float acc = 0.0f;
    for (int k = 0; k < 64; k++) acc += g_Q[i * 64 + k] * sC[k * 64 + k2];
    g_QC[gid] = acc;
}

__global__ void colsum_bt_kernel() {
    __shared__ float red[256];
    int b = blockIdx.x, tid = threadIdx.x;
    float s = 0.0f;
    for (int r = tid; r < NI; r += 256) s += g_Bt[r * NQ + b];
    red[tid] = s; __syncthreads();
    for (int off = 128; off > 0; off >>= 1) {
        if (tid < off) red[tid] += red[tid + off];
        __syncthreads();
    }
    if (tid == 0) g_bsum[b] = red[0];
}

__global__ void rsuminv_kernel() {
    int gid = blockIdx.x * 256 + threadIdx.x;
    float acc = 0.0f;
    for (int k = 0; k < 64; k++) acc += g_QC[gid * 64 + k] * g_bsum[k];
    g_rinv[gid] = 1.0f / acc;
}

__global__ void scale_qc_bf_kernel() {
    int gid = blockIdx.x * 256 + threadIdx.x;
    float v = g_QC[gid] * g_rinv[gid >> 6];
    g_QCbf[gid] = __float2bfloat16(v);
}

__global__ void cvt_bt_kernel() {
    int gid = blockIdx.x * 256 + threadIdx.x;
    g_Btbf[gid] = __float2bfloat16(g_Bt[gid]);
}

__global__ void cvt_s_kernel() {
    int gid = blockIdx.x * 256 + threadIdx.x;
    g_Sbf[gid] = __float2bfloat16(g_S[gid] * g_minv[gid >> 11]);
}

__global__ void rowsum_M_kernel() {
    __shared__ float red[256];
    int row = blockIdx.x, tid = threadIdx.x;
    float s = 0.0f;
    for (int j = tid; j < NI; j += 256) s += g_M[row * NI + j];
    red[tid] = s; __syncthreads();
    for (int off = 128; off > 0; off >>= 1) {
        if (tid < off) red[tid] += red[tid + off];
        __syncthreads();
    }
    if (tid == 0) g_mrow[row] = red[0];
}

__global__ void matvec_minv_kernel() {
    __shared__ float red[256];
    int row = blockIdx.x, tid = threadIdx.x;
    float s = 0.0f;
    for (int j = tid; j < NU; j += 256) s += g_S[row * NU + j] * g_mrow[j];
    red[tid] = s; __syncthreads();
    for (int off = 128; off > 0; off >>= 1) {
        if (tid < off) red[tid] += red[tid + off];
        __syncthreads();
    }
    if (tid == 0) g_minv[row] = 1.0f / red[0];
}

// ---------------- WMMA bf16 GEMM (HMMA path, base sm_103 PTX) ----------------
// D[128,128] per CTA: D = A @ B^T, A [M,K] and B [N,K] both K-major bf16.
// K split into 32-wide chunks; segment1 (nch1) then segment2 (nch2).
// mode 0: fp32 D -> outp.  mode 1: sigmoid(D) - 1000*F -> outp.

#define WSM_A(s) ((s) * 10240)
#define WSM_B(s) (20480 + (s) * 10240)
#define WSM_TOTAL 69632
#define LDSM 40

__device__ __forceinline__ uint32_t smem_u32(const void* p) {
    uint32_t a;
    asm("{ .reg .u64 t; cvta.to.shared.u64 t, %1; cvt.u32.u64 %0, t; }"
        : "=r"(a) : "l"(p));
    return a;
}

__device__ __forceinline__ void cp16(uint32_t s, const void* g) {
    asm volatile("cp.async.cg.shared.global [%0], [%1], 16;" :: "r"(s), "l"(g));
}

__global__ __launch_bounds__(256, 2)
void wmma_gemm(const __nv_bfloat16* __restrict__ A1, int ldA1,
               const __nv_bfloat16* __restrict__ B1, int ldB1, int nch1,
               const __nv_bfloat16* __restrict__ A2, int ldA2,
               const __nv_bfloat16* __restrict__ B2, int ldB2, int nch2,
               int mode, int ld_out, const float* __restrict__ F,
               float* __restrict__ outp) {
    extern __shared__ char smem[];
    const int tid = threadIdx.x;
    const int wid = tid >> 5;
    const int wr = wid >> 1;          // warp row 0..3 -> 32 rows each
    const int wc = wid & 1;           // warp col 0..1 -> 64 cols each
    const int col0 = blockIdx.x * 128;
    const int row0 = blockIdx.y * 128;
    const int nch = nch1 + nch2;
    const uint32_t sb = smem_u32(smem);

    wmma::fragment<wmma::accumulator, 16, 16, 16, float> acc[2][4];
#pragma unroll
    for (int i = 0; i < 2; i++)
#pragma unroll
        for (int j = 0; j < 4; j++) wmma::fill_fragment(acc[i][j], 0.0f);

    const int lr = tid >> 1;          // 0..127 (row in tile)
    const int lh = tid & 1;           // 0/1 (16-col half)

    auto load_chunk = [&](int c, int s) {
        const __nv_bfloat16 *Ap, *Bp;
        int lA, lB, kk;
        if (c < nch1) { Ap = A1; lA = ldA1; Bp = B1; lB = ldB1; kk = c * 32; }
        else { Ap = A2; lA = ldA2; Bp = B2; lB = ldB2; kk = (c - nch1) * 32; }
        uint32_t sA = sb + WSM_A(s) + (uint32_t)(lr * LDSM + lh * 16) * 2;
        const __nv_bfloat16* gA = Ap + (size_t)(row0 + lr) * lA + kk + lh * 16;
        cp16(sA, gA);
        cp16(sA + 16, gA + 8);
        uint32_t sB = sb + WSM_B(s) + (uint32_t)(lr * LDSM + lh * 16) * 2;
        const __nv_bfloat16* gB = Bp + (size_t)(col0 + lr) * lB + kk + lh * 16;
        cp16(sB, gB);
        cp16(sB + 16, gB + 8);
    };

    load_chunk(0, 0);
    asm volatile("cp.async.commit_group;" ::: "memory");

    for (int c = 0; c < nch; c++) {
        if (c + 1 < nch) {
            load_chunk(c + 1, (c + 1) & 1);
            asm volatile("cp.async.commit_group;" ::: "memory");
            asm volatile("cp.async.wait_group 1;" ::: "memory");
        } else {
            asm volatile("cp.async.wait_group 0;" ::: "memory");
        }
        __syncthreads();
        const __nv_bfloat16* As = (const __nv_bfloat16*)(smem + WSM_A(c & 1));
        const __nv_bfloat16* Bs = (const __nv_bfloat16*)(smem + WSM_B(c & 1));
#pragma unroll
        for (int kf = 0; kf < 2; kf++) {
            wmma::fragment<wmma::matrix_a, 16, 16, 16, __nv_bfloat16, wmma::row_major> af[2];
            wmma::fragment<wmma::matrix_b, 16, 16, 16, __nv_bfloat16, wmma::col_major> bf[4];
#pragma unroll
            for (int i = 0; i < 2; i++)
                wmma::load_matrix_sync(af[i], As + (wr * 32 + i * 16) * LDSM + kf * 16, LDSM);
#pragma unroll
            for (int j = 0; j < 4; j++)
                wmma::load_matrix_sync(bf[j], Bs + (wc * 64 + j * 16) * LDSM + kf * 16, LDSM);
#pragma unroll
            for (int i = 0; i < 2; i++)
#pragma unroll
                for (int j = 0; j < 4; j++)
                    wmma::mma_sync(acc[i][j], af[i], bf[j], acc[i][j]);
        }
        __syncthreads();
    }

    if (mode == 0) {
#pragma unroll
        for (int i = 0; i < 2; i++)
#pragma unroll
            for (int j = 0; j < 4; j++)
                wmma::store_matrix_sync(
                    outp + (size_t)(row0 + wr * 32 + i * 16) * ld_out
                         + col0 + wc * 64 + j * 16,
                    acc[i][j], ld_out, wmma::mem_row_major);
    } else {
        float* stag = (float*)smem;  // 128 x 132
#pragma unroll
        for (int i = 0; i < 2; i++)
#pragma unroll
            for (int j = 0; j < 4; j++)
                wmma::store_matrix_sync(
                    stag + (wr * 32 + i * 16) * 132 + wc * 64 + j * 16,
                    acc[i][j], 132, wmma::mem_row_major);
        __syncthreads();
#pragma unroll
        for (int it = 0; it < 64; it++) {
            int idx = tid + it * 256;
            int rr = idx >> 7, cc = idx & 127;
            size_t o = (size_t)(row0 + rr) * ld_out + col0 + cc;
            float v = stag[rr * 132 + cc];
            outp[o] = 1.0f / (1.0f + __expf(-v)) - 1000.0f * F[o];
        }
    }
}

// ---------------- host orchestration ----------------
extern "C" void kernel_launch(void* const* d_in, const int* in_sizes, int n_in,
                              void* d_out, int out_size) {
    (void)in_sizes; (void)n_in; (void)out_size;
    const float* F = (const float*)d_in[0];
    float* out = (float*)d_out;

    float *pM, *pMt, *pQ, *pQ2, *pBt, *pQC, *pS, *pG;
    __nv_bfloat16 *pMbf, *pMtbf, *pSbf, *pQCbf, *pBtbf;
    cudaGetSymbolAddress((void**)&pM, g_M);
    cudaGetSymbolAddress((void**)&pMt, g_Mt);
    cudaGetSymbolAddress((void**)&pQ, g_Q);
    cudaGetSymbolAddress((void**)&pQ2, g_Q2);
    cudaGetSymbolAddress((void**)&pBt, g_Bt);
    cudaGetSymbolAddress((void**)&pQC, g_QC);
    cudaGetSymbolAddress((void**)&pS, g_S);
    cudaGetSymbolAddress((void**)&pG, g_G);
    cudaGetSymbolAddress((void**)&pMbf, g_Mbf);
    cudaGetSymbolAddress((void**)&pMtbf, g_Mtbf);
    cudaGetSymbolAddress((void**)&pSbf, g_Sbf);
    cudaGetSymbolAddress((void**)&pQCbf, g_QCbf);
    cudaGetSymbolAddress((void**)&pBtbf, g_Btbf);

    cudaFuncSetAttribute(wmma_gemm, cudaFuncAttributeMaxDynamicSharedMemorySize,
                         WSM_TOTAL);

    // normalization + M/Mt (+bf16 copies)
    rowsum_du_kernel<<<NU, 256>>>(F);
    colsum_di_kernel<<<NI / 256, 256>>>(F);
    build_M_kernel<<<dim3(NI / 32, NU / 32), dim3(32, 8)>>>(F);

    // S = M M^T via HMMA (fp32 out)
    wmma_gemm<<<dim3(NU / 128, NU / 128), 256, WSM_TOTAL>>>(
        pMbf, NI, pMbf, NI, NI / 32,
        pMbf, NI, pMbf, NI, 0,
        0, NU, (const float*)0, pS);

    // Q0 Gaussian; subspace iteration Q <- cholQR(S @ Q)
    rng_kernel<<<(NU * NQ) / 256, 256>>>(pQ);
    float* cur = pQ;
    float* nxt = pQ2;
    for (int it = 0; it < NITER; it++) {
        zero_kernel<<<(NU * NQ) / 256, 256>>>(nxt, NU * NQ);
        skinny_gemm<<<dim3(NU / 64, 8), 256>>>(nxt, pS, cur, NU, NU / 8);
        gram_part_kernel<<<NU / 128, 256>>>(nxt);
        chol_linv_kernel<<<1, 64>>>(NU / 128);
        trsm_apply_kernel<<<NU / 4, 256>>>(nxt);
        float* t = cur; cur = nxt; nxt = t;
    }
    // NITER even -> cur == pQ

    // Bt = M^T Q; G = Bt^T Bt; eigensolve -> C; QC = Q C
    zero_kernel<<<(NI * NQ) / 256, 256>>>(pBt, NI * NQ);
    skinny_gemm<<<dim3(NI / 64, 2), 256>>>(pBt, pMt, pQ, NU, NU / 2);
    zero_kernel<<<(NQ * NQ + 255) / 256, 256>>>(pG, NQ * NQ);
    gram_kernel<<<NI / 128, 256>>>(pBt);
    jacobi_kernel<<<1, 256>>>();
    qc_kernel<<<(NU * NQ) / 256, 256>>>();

    // row-sum inverses; bf16 conversions with scales folded in
    colsum_bt_kernel<<<NQ, 256>>>();
    rsuminv_kernel<<<NU / 256, 256>>>();
    scale_qc_bf_kernel<<<(NU * NQ) / 256, 256>>>();
    cvt_bt_kernel<<<(NI * NQ) / 256, 256>>>();
    rowsum_M_kernel<<<NU, 256>>>();
    matvec_minv_kernel<<<NU, 256>>>();
    cvt_s_kernel<<<(NU * NU) / 256, 256>>>();

    // fused final: out = sigmoid([Sbf|QCbf] @ [Mtbf|Btbf]^T) - 1000 F
    wmma_gemm<<<dim3(NI / 128, NU / 128), 256, WSM_TOTAL>>>(
        pSbf, NU, pMtbf, NU, NU / 32,
        pQCbf, NQ, pBtbf, NQ, 2,
        1, NI, F, out);
}

// round 9
// speedup vs baseline: 5.7005x; 1.1487x over previous
#include <cuda_runtime.h>
#include <cuda_bf16.h>
#include <mma.h>
#include <cstdint>

using namespace nvcuda;

#define NU 2048
#define NI 8192
#define NQ 64
#define NROUND 4
#define NSWEEP 8

// ---------------- device globals ----------------
__device__ float g_M[NU * NI];
__device__ float g_Mt[NI * NU];
__device__ float g_S[NU * NU];
__device__ __nv_bfloat16 g_Mbf[NU * NI];
__device__ __nv_bfloat16 g_Mtbf[NI * NU];
__device__ __nv_bfloat16 g_Sbf[NU * NU];
__device__ __nv_bfloat16 g_QCbf[NU * NQ];
__device__ __nv_bfloat16 g_Btbf[NI * NQ];
__device__ float g_Q[NU * NQ];
__device__ float g_Q2[NU * NQ];
__device__ float g_Bt[NI * NQ];
__device__ float g_QC[NU * NQ];
__device__ float g_G[NQ * NQ];
__device__ float g_Gp[16 * NQ * NQ];
__device__ float g_Li[NQ * NQ];
__device__ float g_C[NQ * NQ];
__device__ float g_du[NU];
__device__ float g_di[NI];
__device__ float g_mrow[NU];
__device__ float g_minv[NU];
__device__ float g_rinv[NU];
__device__ float g_bsum[NQ];

// ---------------- small helpers ----------------
__global__ void zero_kernel(float* __restrict__ p, int n) {
    int i = blockIdx.x * 256 + threadIdx.x;
    if (i < n) p[i] = 0.0f;
}

__global__ void rowsum_du_kernel(const float* __restrict__ F) {
    __shared__ float red[256];
    int row = blockIdx.x, tid = threadIdx.x;
    float s = 0.0f;
    for (int j = tid; j < NI; j += 256) s += F[row * NI + j];
    red[tid] = s; __syncthreads();
    for (int off = 128; off > 0; off >>= 1) {
        if (tid < off) red[tid] += red[tid + off];
        __syncthreads();
    }
    if (tid == 0) g_du[row] = rsqrtf(red[0] + 1.0f);
}

__global__ void colsum_di_kernel(const float* __restrict__ F) {
    int j = blockIdx.x * 256 + threadIdx.x;
    float s = 0.0f;
    for (int i = 0; i < NU; i++) s += F[i * NI + j];
    g_di[j] = rsqrtf(s + 1.0f);
}

__global__ void build_M_kernel(const float* __restrict__ F) {
    __shared__ float sh[32][33];
    int tx = threadIdx.x, ty = threadIdx.y;
    int col0 = blockIdx.x * 32, row0 = blockIdx.y * 32;
    int j = col0 + tx;
    float dj = g_di[j];
#pragma unroll
    for (int k = 0; k < 4; k++) {
        int i = row0 + ty + k * 8;
        float v = g_du[i] * F[i * NI + j] * dj;
        g_M[i * NI + j] = v;
        g_Mbf[i * NI + j] = __float2bfloat16(v);
        sh[ty + k * 8][tx] = v;
    }
    __syncthreads();
#pragma unroll
    for (int k = 0; k < 4; k++) {
        int jj = col0 + ty + k * 8;
        float v = sh[tx][ty + k * 8];
        g_Mt[jj * NU + row0 + tx] = v;
        g_Mtbf[jj * NU + row0 + tx] = __float2bfloat16(v);
    }
}

__device__ __forceinline__ unsigned int hashu(unsigned int x) {
    x ^= x >> 16; x *= 0x7feb352dU; x ^= x >> 15; x *= 0x846ca68bU; x ^= x >> 16;
    return x;
}

__global__ void rng_kernel(float* __restrict__ p) {
    int gid = blockIdx.x * 256 + threadIdx.x;
    unsigned int h1 = hashu(2u * gid + 17u);
    unsigned int h2 = hashu(2u * gid + 18u);
    float u1 = ((h1 >> 9) + 0.5f) * (1.0f / 8388608.0f);
    float u2 = ((h2 >> 9) + 0.5f) * (1.0f / 8388608.0f);
    p[gid] = sqrtf(-2.0f * __logf(u1)) * __cosf(6.2831853f * u2);
}

// out[R,64] = A[R,K] @ W[K,64]; one block per 64 rows, full K, no atomics.
__global__ __launch_bounds__(256) void skinny_gemm(
    float* __restrict__ out, const float* __restrict__ A,
    const float* __restrict__ W, int lda, int K) {
    __shared__ float AsT[16][64];
    __shared__ float Ws[16][64];
    int tid = threadIdx.x;
    int tx = tid & 15, ty = tid >> 4;
    int row0 = blockIdx.x * 64;
    int aR = tid >> 2, aC = tid & 3;
    int wK = tid >> 4, wQ = tid & 15;
    float acc[4][4] = {};
    for (int kb = 0; kb < K; kb += 16) {
        float4 av = *(const float4*)(A + (size_t)(row0 + aR) * lda + kb + aC * 4);
        AsT[aC * 4 + 0][aR] = av.x; AsT[aC * 4 + 1][aR] = av.y;
        AsT[aC * 4 + 2][aR] = av.z; AsT[aC * 4 + 3][aR] = av.w;
        *(float4*)(&Ws[wK][wQ * 4]) = *(const float4*)(W + (kb + wK) * NQ + wQ * 4);
        __syncthreads();
#pragma unroll
        for (int k = 0; k < 16; k++) {
            float4 a = *(float4*)&AsT[k][ty * 4];
            float4 w = *(float4*)&Ws[k][tx * 4];
            float aa[4] = {a.x, a.y, a.z, a.w};
            float ww[4] = {w.x, w.y, w.z, w.w};
#pragma unroll
            for (int i = 0; i < 4; i++)
#pragma unroll
                for (int j = 0; j < 4; j++) acc[i][j] += aa[i] * ww[j];
        }
        __syncthreads();
    }
#pragma unroll
    for (int i = 0; i < 4; i++)
#pragma unroll
        for (int j = 0; j < 4; j++)
            out[(row0 + ty * 4 + i) * NQ + tx * 4 + j] = acc[i][j];
}

// atomic Gram into g_G (used once, for Bt); g_G pre-zeroed
__global__ __launch_bounds__(256) void gram_kernel(const float* __restrict__ Y) {
    __shared__ float Ys[16][64];
    int tid = threadIdx.x;
    int tx = tid & 15, ty = tid >> 4;
    int wK = tid >> 4, wQ = tid & 15;
    int base = blockIdx.x * 128;
    float acc[4][4] = {};
    for (int c = 0; c < 8; c++) {
        *(float4*)&Ys[wK][wQ * 4] =
            *(const float4*)(Y + (base + c * 16 + wK) * NQ + wQ * 4);
        __syncthreads();
#pragma unroll
        for (int r = 0; r < 16; r++) {
            float4 a = *(float4*)&Ys[r][ty * 4];
            float4 b = *(float4*)&Ys[r][tx * 4];
            float aa[4] = {a.x, a.y, a.z, a.w};
            float bb[4] = {b.x, b.y, b.z, b.w};
#pragma unroll
            for (int i = 0; i < 4; i++)
#pragma unroll
                for (int j = 0; j < 4; j++) acc[i][j] += aa[i] * bb[j];
        }
        __syncthreads();
    }
#pragma unroll
    for (int i = 0; i < 4; i++)
#pragma unroll
        for (int j = 0; j < 4; j++)
            atomicAdd(&g_G[(ty * 4 + i) * NQ + tx * 4 + j], acc[i][j]);
}

// per-block Gram partials (no atomics) for the QR loop
__global__ __launch_bounds__(256) void gram_part_kernel(const float* __restrict__ Y) {
    __shared__ float Ys[16][64];
    int tid = threadIdx.x;
    int tx = tid & 15, ty = tid >> 4;
    int wK = tid >> 4, wQ = tid & 15;
    int base = blockIdx.x * 128;
    float acc[4][4] = {};
    for (int c = 0; c < 8; c++) {
        *(float4*)&Ys[wK][wQ * 4] =
            *(const float4*)(Y + (base + c * 16 + wK) * NQ + wQ * 4);
        __syncthreads();
#pragma unroll
        for (int r = 0; r < 16; r++) {
            float4 a = *(float4*)&Ys[r][ty * 4];
            float4 b = *(float4*)&Ys[r][tx * 4];
            float aa[4] = {a.x, a.y, a.z, a.w};
            float bb[4] = {b.x, b.y, b.z, b.w};
#pragma unroll
            for (int i = 0; i < 4; i++)
#pragma unroll
                for (int j = 0; j < 4; j++) acc[i][j] += aa[i] * bb[j];
        }
        __syncthreads();
    }
    float* dst = g_Gp + blockIdx.x * (NQ * NQ);
#pragma unroll
    for (int i = 0; i < 4; i++)
#pragma unroll
        for (int j = 0; j < 4; j++)
            dst[(ty * 4 + i) * NQ + tx * 4 + j] = acc[i][j];
}

// sum Gram partials (256 thr) -> Cholesky (64 thr) -> explicit Linv
__global__ __launch_bounds__(256) void chol_linv_kernel(int nparts) {
    __shared__ float sA[64][65];
    __shared__ float sX[64][65];
    int tid = threadIdx.x;
    for (int o = tid; o < 4096; o += 256) {
        int r = o >> 6, c = o & 63;
        float s = 0.0f;
        for (int p = 0; p < nparts; p++) s += g_Gp[p * 4096 + o];
        sA[r][c] = s;
    }
    __syncthreads();
    for (int k = 0; k < 64; k++) {
        if (tid == k) sA[k][k] = sqrtf(fmaxf(sA[k][k], 1e-30f));
        __syncthreads();
        if (tid > k && tid < 64) sA[tid][k] /= sA[k][k];
        __syncthreads();
        if (tid > k && tid < 64)
            for (int j = k + 1; j <= tid; j++)
                sA[tid][j] -= sA[tid][k] * sA[j][k];
        __syncthreads();
    }
    if (tid < 64) {
        int c = tid;
        for (int i = c; i < 64; i++) {
            float acc = (i == c) ? 1.0f : 0.0f;
            for (int k = c; k < i; k++) acc -= sA[i][k] * sX[k][c];
            float v = acc / sA[i][i];
            sX[i][c] = v;
            g_Li[i * 64 + c] = v;
        }
    }
}

// Y <- Y * Linv^T ; 4 rows/block
__global__ __launch_bounds__(256) void trsm_apply_kernel(float* __restrict__ Y) {
    __shared__ float sLi[64][65];
    __shared__ float sY[4][64];
    int tid = threadIdx.x;
    for (int i = tid; i < 4096; i += 256) sLi[i >> 6][i & 63] = g_Li[i];
    int lr = tid >> 6, j = tid & 63;
    int r = blockIdx.x * 4 + lr;
    sY[lr][j] = Y[r * NQ + j];
    __syncthreads();
    float acc = 0.0f;
    for (int k = 0; k <= j; k++) acc += sY[lr][k] * sLi[j][k];
    Y[r * NQ + j] = acc;
}

__global__ __launch_bounds__(256) void jacobi_kernel() {
    __shared__ float sA[64][65];
    __shared__ float sV[64][65];
    __shared__ float pc[32], ps[32];
    __shared__ int pp[32], pq[32];
    __shared__ float lam[64];
    __shared__ float smax;
    int tid = threadIdx.x;
    for (int o = tid; o < 4096; o += 256) {
        int r = o >> 6, c = o & 63;
        sA[r][c] = g_G[o];
        sV[r][c] = (r == c) ? 1.0f : 0.0f;
    }
    __syncthreads();
    for (int sweep = 0; sweep < NSWEEP; sweep++) {
        for (int r = 0; r < 63; r++) {
            if (tid < 32) {
                int p, q;
                if (tid == 0) { p = 63; q = r; }
                else { p = (r + tid) % 63; q = (r - tid + 63) % 63; }
                float app = sA[p][p], aqq = sA[q][q], apq = sA[p][q];
                float c = 1.0f, s = 0.0f;
                if (fabsf(apq) > 1e-20f) {
                    float tau = (aqq - app) / (2.0f * apq);
                    float t = ((tau >= 0.0f) ? 1.0f : -1.0f) /
                              (fabsf(tau) + sqrtf(1.0f + tau * tau));
                    c = rsqrtf(1.0f + t * t);
                    s = t * c;
                }
                pp[tid] = p; pq[tid] = q; pc[tid] = c; ps[tid] = s;
            }
            __syncthreads();
            for (int it = tid; it < 4096; it += 256) {
                int pr = it >> 7;
                int rest = it & 127;
                int i = rest & 63;
                float c = pc[pr], s = ps[pr];
                int p = pp[pr], q = pq[pr];
                if (rest < 64) {
                    float x = sA[i][p], y = sA[i][q];
                    sA[i][p] = c * x - s * y;
                    sA[i][q] = s * x + c * y;
                } else {
                    float x = sV[i][p], y = sV[i][q];
                    sV[i][p] = c * x - s * y;
                    sV[i][q] = s * x + c * y;
                }
            }
            __syncthreads();
            for (int it = tid; it < 2048; it += 256) {
                int pr = it >> 6;
                int j = it & 63;
                float c = pc[pr], s = ps[pr];
                int p = pp[pr], q = pq[pr];
                float x = sA[p][j], y = sA[q][j];
                sA[p][j] = c * x - s * y;
                sA[q][j] = s * x + c * y;
            }
            __syncthreads();
        }
    }
    if (tid < 64) lam[tid] = fmaxf(sA[tid][tid], 0.0f);
    __syncthreads();
    if (tid == 0) {
        float m = 0.0f;
        for (int k = 0; k < 64; k++) m = fmaxf(m, lam[k]);
        smax = m;
    }
    __syncthreads();
    if (tid < 64) {
        float l = lam[tid];
        lam[tid] = l * sqrtf(l) / (smax * smax);
    }
    __syncthreads();
    for (int o = tid; o < 4096; o += 256) {
        int i = o >> 6, j = o & 63;
        float acc = 0.0f;
        for (int k = 0; k < 64; k++) acc += sV[i][k] * lam[k] * sV[j][k];
        g_C[o] = acc;
    }
}

__global__ __launch_bounds__(256) void qc_kernel() {
    __shared__ float sC[64 * 64];
    int tid = threadIdx.x;
    for (int i = tid; i < 4096; i += 256) sC[i] = g_C[i];
    __syncthreads();
    int gid = blockIdx.x * 256 + tid;
    int i = gid >> 6, k2 = gid & 63;
    float acc = 0.0f;
    for (int k = 0; k < 64; k++) acc += g_Q[i * 64 + k] * sC[k * 64 + k2];
    g_QC[gid] = acc;
}

__global__ void colsum_bt_kernel() {
    __shared__ float red[256];
    int b = blockIdx.x, tid = threadIdx.x;
    float s = 0.0f;
    for (int r = tid; r < NI; r += 256) s += g_Bt[r * NQ + b];
    red[tid] = s; __syncthreads();
    for (int off = 128; off > 0; off >>= 1) {
        if (tid < off) red[tid] += red[tid + off];
        __syncthreads();
    }
    if (tid == 0) g_bsum[b] = red[0];
}

__global__ void rsuminv_kernel() {
    int gid = blockIdx.x * 256 + threadIdx.x;
    float acc = 0.0f;
    for (int k = 0; k < 64; k++) acc += g_QC[gid * 64 + k] * g_bsum[k];
    g_rinv[gid] = 1.0f / acc;
}

__global__ void scale_qc_bf_kernel() {
    int gid = blockIdx.x * 256 + threadIdx.x;
    float v = g_QC[gid] * g_rinv[gid >> 6];
    g_QCbf[gid] = __float2bfloat16(v);
}

__global__ void cvt_bt_kernel() {
    int gid = blockIdx.x * 256 + threadIdx.x;
    g_Btbf[gid] = __float2bfloat16(g_Bt[gid]);
}

__global__ void cvt_s_kernel() {
    int gid = blockIdx.x * 256 + threadIdx.x;
    g_Sbf[gid] = __float2bfloat16(g_S[gid] * g_minv[gid >> 11]);
}

__global__ void rowsum_M_kernel() {
    __shared__ float red[256];
    int row = blockIdx.x, tid = threadIdx.x;
    float s = 0.0f;
    for (int j = tid; j < NI; j += 256) s += g_M[row * NI + j];
    red[tid] = s; __syncthreads();
    for (int off = 128; off > 0; off >>= 1) {
        if (tid < off) red[tid] += red[tid + off];
        __syncthreads();
    }
    if (tid == 0) g_mrow[row] = red[0];
}

__global__ void matvec_minv_kernel() {
    __shared__ float red[256];
    int row = blockIdx.x, tid = threadIdx.x;
    float s = 0.0f;
    for (int j = tid; j < NU; j += 256) s += g_S[row * NU + j] * g_mrow[j];
    red[tid] = s; __syncthreads();
    for (int off = 128; off > 0; off >>= 1) {
        if (tid < off) red[tid] += red[tid + off];
        __syncthreads();
    }
    if (tid == 0) g_minv[row] = 1.0f / red[0];
}

// ---------------- WMMA bf16 GEMM ----------------
// D[128,128] per CTA: D = A @ B^T, A [M,K] and B [N,K] both K-major bf16.
// K split into 64-wide chunks; segment1 (nch1) then segment2 (nch2).
// mode 0: fp32 D -> outp.  mode 1: sigmoid(D) - 1000*F -> outp.

#define LDSM 72
#define WSM_A(s) ((s) * 18432)
#define WSM_B(s) (36864 + (s) * 18432)
#define WSM_TOTAL 73728

__device__ __forceinline__ uint32_t smem_u32(const void* p) {
    uint32_t a;
    asm("{ .reg .u64 t; cvta.to.shared.u64 t, %1; cvt.u32.u64 %0, t; }"
        : "=r"(a) : "l"(p));
    return a;
}

__device__ __forceinline__ void cp16(uint32_t s, const void* g) {
    asm volatile("cp.async.cg.shared.global [%0], [%1], 16;" :: "r"(s), "l"(g));
}

__global__ __launch_bounds__(256, 2)
void wmma_gemm(const __nv_bfloat16* __restrict__ A1, int ldA1,
               const __nv_bfloat16* __restrict__ B1, int ldB1, int nch1,
               const __nv_bfloat16* __restrict__ A2, int ldA2,
               const __nv_bfloat16* __restrict__ B2, int ldB2, int nch2,
               int mode, int ld_out, const float* __restrict__ F,
               float* __restrict__ outp) {
    extern __shared__ char smem[];
    const int tid = threadIdx.x;
    const int wid = tid >> 5;
    const int wr = wid >> 1;
    const int wc = wid & 1;
    const int col0 = blockIdx.x * 128;
    const int row0 = blockIdx.y * 128;
    const int nch = nch1 + nch2;
    const uint32_t sb = smem_u32(smem);

    wmma::fragment<wmma::accumulator, 16, 16, 16, float> acc[2][4];
#pragma unroll
    for (int i = 0; i < 2; i++)
#pragma unroll
        for (int j = 0; j < 4; j++) wmma::fill_fragment(acc[i][j], 0.0f);

    const int lr = tid >> 1;   // row 0..127
    const int lh = tid & 1;    // 32-col half

    auto load_chunk = [&](int c, int s) {
        const __nv_bfloat16 *Ap, *Bp;
        int lA, lB, kk;
        if (c < nch1) { Ap = A1; lA = ldA1; Bp = B1; lB = ldB1; kk = c * 64; }
        else { Ap = A2; lA = ldA2; Bp = B2; lB = ldB2; kk = (c - nch1) * 64; }
        uint32_t sA = sb + WSM_A(s) + (uint32_t)(lr * LDSM + lh * 32) * 2;
        const __nv_bfloat16* gA = Ap + (size_t)(row0 + lr) * lA + kk + lh * 32;
        cp16(sA, gA); cp16(sA + 16, gA + 8);
        cp16(sA + 32, gA + 16); cp16(sA + 48, gA + 24);
        uint32_t sB = sb + WSM_B(s) + (uint32_t)(lr * LDSM + lh * 32) * 2;
        const __nv_bfloat16* gB = Bp + (size_t)(col0 + lr) * lB + kk + lh * 32;
        cp16(sB, gB); cp16(sB + 16, gB + 8);
        cp16(sB + 32, gB + 16); cp16(sB + 48, gB + 24);
    };

    load_chunk(0, 0);
    asm volatile("cp.async.commit_group;" ::: "memory");

    for (int c = 0; c < nch; c++) {
        if (c + 1 < nch) {
            load_chunk(c + 1, (c + 1) & 1);
            asm volatile("cp.async.commit_group;" ::: "memory");
            asm volatile("cp.async.wait_group 1;" ::: "memory");
        } else {
            asm volatile("cp.async.wait_group 0;" ::: "memory");
        }
        __syncthreads();
        const __nv_bfloat16* As = (const __nv_bfloat16*)(smem + WSM_A(c & 1));
        const __nv_bfloat16* Bs = (const __nv_bfloat16*)(smem + WSM_B(c & 1));
#pragma unroll
        for (int kf = 0; kf < 4; kf++) {
            wmma::fragment<wmma::matrix_a, 16, 16, 16, __nv_bfloat16, wmma::row_major> af[2];
            wmma::fragment<wmma::matrix_b, 16, 16, 16, __nv_bfloat16, wmma::col_major> bf[4];
#pragma unroll
            for (int i = 0; i < 2; i++)
                wmma::load_matrix_sync(af[i], As + (wr * 32 + i * 16) * LDSM + kf * 16, LDSM);
#pragma unroll
            for (int j = 0; j < 4; j++)
                wmma::load_matrix_sync(bf[j], Bs + (wc * 64 + j * 16) * LDSM + kf * 16, LDSM);
#pragma unroll
            for (int i = 0; i < 2; i++)
#pragma unroll
                for (int j = 0; j < 4; j++)
                    wmma::mma_sync(acc[i][j], af[i], bf[j], acc[i][j]);
        }
        __syncthreads();
    }

    if (mode == 0) {
#pragma unroll
        for (int i = 0; i < 2; i++)
#pragma unroll
            for (int j = 0; j < 4; j++)
                wmma::store_matrix_sync(
                    outp + (size_t)(row0 + wr * 32 + i * 16) * ld_out
                         + col0 + wc * 64 + j * 16,
                    acc[i][j], ld_out, wmma::mem_row_major);
    } else {
        float* stag = (float*)smem;  // 128 x 132
#pragma unroll
        for (int i = 0; i < 2; i++)
#pragma unroll
            for (int j = 0; j < 4; j++)
                wmma::store_matrix_sync(
                    stag + (wr * 32 + i * 16) * 132 + wc * 64 + j * 16,
                    acc[i][j], 132, wmma::mem_row_major);
        __syncthreads();
#pragma unroll
        for (int it = 0; it < 64; it++) {
            int idx = tid + it * 256;
            int rr = idx >> 7, cc = idx & 127;
            size_t o = (size_t)(row0 + rr) * ld_out + col0 + cc;
            float v = stag[rr * 132 + cc];
            outp[o] = 1.0f / (1.0f + __expf(-v)) - 1000.0f * F[o];
        }
    }
}

// ---------------- host orchestration ----------------
extern "C" void kernel_launch(void* const* d_in, const int* in_sizes, int n_in,
                              void* d_out, int out_size) {
    (void)in_sizes; (void)n_in; (void)out_size;
    const float* F = (const float*)d_in[0];
    float* out = (float*)d_out;

    float *pM, *pMt, *pQ, *pQ2, *pBt, *pQC, *pS, *pG;
    __nv_bfloat16 *pMbf, *pMtbf, *pSbf, *pQCbf, *pBtbf;
    cudaGetSymbolAddress((void**)&pM, g_M);
    cudaGetSymbolAddress((void**)&pMt, g_Mt);
    cudaGetSymbolAddress((void**)&pQ, g_Q);
    cudaGetSymbolAddress((void**)&pQ2, g_Q2);
    cudaGetSymbolAddress((void**)&pBt, g_Bt);
    cudaGetSymbolAddress((void**)&pQC, g_QC);
    cudaGetSymbolAddress((void**)&pS, g_S);
    cudaGetSymbolAddress((void**)&pG, g_G);
    cudaGetSymbolAddress((void**)&pMbf, g_Mbf);
    cudaGetSymbolAddress((void**)&pMtbf, g_Mtbf);
    cudaGetSymbolAddress((void**)&pSbf, g_Sbf);
    cudaGetSymbolAddress((void**)&pQCbf, g_QCbf);
    cudaGetSymbolAddress((void**)&pBtbf, g_Btbf);

    cudaFuncSetAttribute(wmma_gemm, cudaFuncAttributeMaxDynamicSharedMemorySize,
                         WSM_TOTAL);

    // normalization + M/Mt (+bf16 copies)
    rowsum_du_kernel<<<NU, 256>>>(F);
    colsum_di_kernel<<<NI / 256, 256>>>(F);
    build_M_kernel<<<dim3(NI / 32, NU / 32), dim3(32, 8)>>>(F);

    // S = M M^T via HMMA (fp32 out)
    wmma_gemm<<<dim3(NU / 128, NU / 128), 256, WSM_TOTAL>>>(
        pMbf, NI, pMbf, NI, NI / 64,
        pMbf, NI, pMbf, NI, 0,
        0, NU, (const float*)0, pS);

    // Q0 Gaussian; 4 rounds of (Q <- S·S·Q ; cholQR)
    rng_kernel<<<(NU * NQ) / 256, 256>>>(pQ);
    for (int r = 0; r < NROUND; r++) {
        skinny_gemm<<<NU / 64, 256>>>(pQ2, pS, pQ, NU, NU);
        skinny_gemm<<<NU / 64, 256>>>(pQ, pS, pQ2, NU, NU);
        gram_part_kernel<<<NU / 128, 256>>>(pQ);
        chol_linv_kernel<<<1, 256>>>(NU / 128);
        trsm_apply_kernel<<<NU / 4, 256>>>(pQ);
    }

    // Bt = M^T Q; G = Bt^T Bt; eigensolve -> C; QC = Q C
    skinny_gemm<<<NI / 64, 256>>>(pBt, pMt, pQ, NU, NU);
    zero_kernel<<<(NQ * NQ + 255) / 256, 256>>>(pG, NQ * NQ);
    gram_kernel<<<NI / 128, 256>>>(pBt);
    jacobi_kernel<<<1, 256>>>();
    qc_kernel<<<(NU * NQ) / 256, 256>>>();

    // row-sum inverses; bf16 conversions with scales folded in
    colsum_bt_kernel<<<NQ, 256>>>();
    rsuminv_kernel<<<NU / 256, 256>>>();
    scale_qc_bf_kernel<<<(NU * NQ) / 256, 256>>>();
    cvt_bt_kernel<<<(NI * NQ) / 256, 256>>>();
    rowsum_M_kernel<<<NU, 256>>>();
    matvec_minv_kernel<<<NU, 256>>>();
    cvt_s_kernel<<<(NU * NU) / 256, 256>>>();

    // fused final: out = sigmoid([Sbf|QCbf] @ [Mtbf|Btbf]^T) - 1000 F
    wmma_gemm<<<dim3(NI / 128, NU / 128), 256, WSM_TOTAL>>>(
        pSbf, NU, pMtbf, NU, NU / 64,
        pQCbf, NQ, pBtbf, NQ, 1,
        1, NI, F, out);
}